// round 4
// baseline (speedup 1.0000x reference)
#include <cuda_runtime.h>
#include <cuda_bf16.h>
#include <math.h>

// ---------------------------------------------------------------------------
// GCN + TopK pooling stack (3 layers), B=128 graphs, N=1024 nodes, H=128.
// ---------------------------------------------------------------------------

#define Bg   128
#define Npg  1024
#define Hd   128
#define NN1  (Bg*Npg)        // 131072
#define NN2  (Bg*512)        // 65536
#define NN3  (Bg*256)        // 32768
#define EMAX 1048576

// ------------------------- device scratch (no allocs) ----------------------
__device__ __align__(128) float g_h [NN1*Hd];   // h = x @ W
__device__ __align__(128) float g_cv[NN1*Hd];   // conv output (relu'd)
__device__ __align__(128) float g_xs1[NN2*Hd];
__device__ __align__(128) float g_xs2[NN3*Hd];
__device__ __align__(128) float g_xs3[(Bg*128)*Hd];
__device__ float g_dinv[NN1];
__device__ float g_sc[NN1];
__device__ int   g_newid[NN1];
__device__ int   g_cnt[NN1];
__device__ int   g_start[NN1];
__device__ int   g_cursor[NN1];
__device__ int   g_bsum[256];
__device__ int   g_src[EMAX];
__device__ int   g_r0[EMAX], g_c0[EMAX];
__device__ int   g_r1[EMAX], g_c1[EMAX];
__device__ int   g_nE[2];
__device__ float g_pinv[3];

// ------------------------------ f32x2 helpers -------------------------------
__device__ __forceinline__ unsigned long long pack2(float x) {
    unsigned long long r;
    asm("mov.b64 %0, {%1, %1};" : "=l"(r) : "f"(x));
    return r;
}
__device__ __forceinline__ void fma2(unsigned long long& d,
                                     unsigned long long a, unsigned long long b) {
    asm("fma.rn.f32x2 %0, %1, %2, %0;" : "+l"(d) : "l"(a), "l"(b));
}

// ------------------------------- GEMM --------------------------------------
// Out[n,128] = X[n,128] @ W[128,128].
// 128-row tiles, 512 threads, 4x8 micro-tile (acc = 16 u64 = 32 regs).
// B operands read directly as packed u64 pairs from smem.
#define KP 132

__global__ void __launch_bounds__(512, 1)
gemm128(const float* __restrict__ X, const float* __restrict__ W,
        float* __restrict__ Out)
{
    __shared__ float sX[16][KP];   // [k][row]
    __shared__ float sW[16][KP];   // [k][col]
    const int tid = threadIdx.x;
    const int tx = tid & 15;       // 16 col groups of 8 cols
    const int ty = tid >> 4;       // 32 row groups of 4 rows
    const long row0 = (long)blockIdx.x * 128;

    unsigned long long acc[4][4];
#pragma unroll
    for (int i = 0; i < 4; i++)
#pragma unroll
        for (int j = 0; j < 4; j++) acc[i][j] = 0ull;

    for (int k0 = 0; k0 < 128; k0 += 16) {
        // stage W chunk: 512 float4, exactly one per thread
        {
            int kk = tid >> 5, c4 = tid & 31;
            float4 v = ((const float4*)(W + (k0 + kk) * 128))[c4];
            float* d = &sW[kk][c4 * 4];
            d[0] = v.x; d[1] = v.y; d[2] = v.z; d[3] = v.w;
        }
        // stage X chunk transposed: one float4 per thread
        {
            int r = tid >> 2, kq = (tid & 3) * 4;
            float4 v = ((const float4*)(X + (row0 + r) * 128 + k0))[tid & 3];
            sX[kq + 0][r] = v.x; sX[kq + 1][r] = v.y;
            sX[kq + 2][r] = v.z; sX[kq + 3][r] = v.w;
        }
        __syncthreads();

#pragma unroll
        for (int k = 0; k < 16; k++) {
            const unsigned long long* bp =
                (const unsigned long long*)&sW[k][tx * 8];
            unsigned long long B0 = bp[0], B1 = bp[1], B2 = bp[2], B3 = bp[3];
            float4 a = *(const float4*)&sX[k][ty * 4];
            float av[4] = { a.x, a.y, a.z, a.w };
#pragma unroll
            for (int i = 0; i < 4; i++) {
                unsigned long long A = pack2(av[i]);
                fma2(acc[i][0], A, B0);
                fma2(acc[i][1], A, B1);
                fma2(acc[i][2], A, B2);
                fma2(acc[i][3], A, B3);
            }
        }
        __syncthreads();
    }

#pragma unroll
    for (int i = 0; i < 4; i++) {
        float* o = Out + (row0 + ty * 4 + i) * 128 + tx * 8;
        float2* a = (float2*)acc[i];
        *((float4*)o)       = make_float4(a[0].x, a[0].y, a[1].x, a[1].y);
        *((float4*)(o + 4)) = make_float4(a[2].x, a[2].y, a[3].x, a[3].y);
    }
}

// ------------------------- CSR build: hist / scan ---------------------------
__global__ void hist_k(const int* __restrict__ col, int* __restrict__ cnt, int nE) {
    int i = blockIdx.x * blockDim.x + threadIdx.x;
    if (i < nE) atomicAdd(&cnt[col[i]], 1);
}

__global__ void scanA_k(const int* __restrict__ cnt, int* __restrict__ start,
                        int* __restrict__ bsum) {
    __shared__ int s[1024];
    int t = threadIdx.x;
    int i = blockIdx.x * 1024 + t;
    int v = cnt[i];
    s[t] = v;
    __syncthreads();
    for (int o = 1; o < 1024; o <<= 1) {
        int add = (t >= o) ? s[t - o] : 0;
        __syncthreads();
        s[t] += add;
        __syncthreads();
    }
    start[i] = s[t] - v;
    if (t == 1023) bsum[blockIdx.x] = s[t];
}

__global__ void scanB_k(int* bsum, int nb) {   // <<<1,128>>>, nb <= 128
    __shared__ int s[128];
    int t = threadIdx.x;
    int v = (t < nb) ? bsum[t] : 0;
    s[t] = v;
    __syncthreads();
    for (int o = 1; o < 128; o <<= 1) {
        int add = (t >= o) ? s[t - o] : 0;
        __syncthreads();
        s[t] += add;
        __syncthreads();
    }
    if (t < nb) bsum[t] = s[t] - v;
}

__global__ void scanC_k(int* __restrict__ start, const int* __restrict__ bsum,
                        const int* __restrict__ cnt, float* __restrict__ dinv, int n) {
    int i = blockIdx.x * blockDim.x + threadIdx.x;
    if (i >= n) return;
    start[i] += bsum[i >> 10];
    dinv[i] = rsqrtf((float)cnt[i] + 1.0f);
}

__global__ void fill_k(const int* __restrict__ row, const int* __restrict__ col,
                       const int* __restrict__ start, int* __restrict__ cursor,
                       int* __restrict__ src, const int* __restrict__ boundPtr,
                       int maxE) {
    int i = blockIdx.x * blockDim.x + threadIdx.x;
    int bound = boundPtr ? __ldg(boundPtr) : maxE;
    if (i >= bound) return;
    int c = col[i];
    int p = atomicAdd(&cursor[c], 1);
    src[start[c] + p] = row[i];
}

// ---- gather + self + bias + relu + score, fused; x4 edge unroll ------------
__global__ void gather_k(const float* __restrict__ h, const int* __restrict__ start,
                         const int* __restrict__ cnt, const int* __restrict__ src,
                         const float* __restrict__ dinv, const float* __restrict__ b,
                         const float* __restrict__ p, const float* __restrict__ pinv,
                         float* __restrict__ out, float* __restrict__ score, int n) {
    int w = (blockIdx.x * blockDim.x + threadIdx.x) >> 5;
    if (w >= n) return;
    int lane = threadIdx.x & 31;
    float dc = dinv[w];
    int s0 = start[w], d = cnt[w];
    float4 hv = ((const float4*)(h + (long)w * Hd))[lane];
    float4 acc = make_float4(hv.x * dc, hv.y * dc, hv.z * dc, hv.w * dc);

    int e = 0;
    for (; e + 4 <= d; e += 4) {
        int r0 = __ldg(&src[s0 + e]);
        int r1 = __ldg(&src[s0 + e + 1]);
        int r2 = __ldg(&src[s0 + e + 2]);
        int r3 = __ldg(&src[s0 + e + 3]);
        float c0 = __ldg(&dinv[r0]), c1 = __ldg(&dinv[r1]);
        float c2 = __ldg(&dinv[r2]), c3 = __ldg(&dinv[r3]);
        float4 v0 = ((const float4*)(h + (long)r0 * Hd))[lane];
        float4 v1 = ((const float4*)(h + (long)r1 * Hd))[lane];
        float4 v2 = ((const float4*)(h + (long)r2 * Hd))[lane];
        float4 v3 = ((const float4*)(h + (long)r3 * Hd))[lane];
        acc.x = fmaf(v0.x, c0, acc.x); acc.y = fmaf(v0.y, c0, acc.y);
        acc.z = fmaf(v0.z, c0, acc.z); acc.w = fmaf(v0.w, c0, acc.w);
        acc.x = fmaf(v1.x, c1, acc.x); acc.y = fmaf(v1.y, c1, acc.y);
        acc.z = fmaf(v1.z, c1, acc.z); acc.w = fmaf(v1.w, c1, acc.w);
        acc.x = fmaf(v2.x, c2, acc.x); acc.y = fmaf(v2.y, c2, acc.y);
        acc.z = fmaf(v2.z, c2, acc.z); acc.w = fmaf(v2.w, c2, acc.w);
        acc.x = fmaf(v3.x, c3, acc.x); acc.y = fmaf(v3.y, c3, acc.y);
        acc.z = fmaf(v3.z, c3, acc.z); acc.w = fmaf(v3.w, c3, acc.w);
    }
    for (; e < d; e++) {
        int r = __ldg(&src[s0 + e]);
        float cr = __ldg(&dinv[r]);
        float4 v = ((const float4*)(h + (long)r * Hd))[lane];
        acc.x = fmaf(v.x, cr, acc.x); acc.y = fmaf(v.y, cr, acc.y);
        acc.z = fmaf(v.z, cr, acc.z); acc.w = fmaf(v.w, cr, acc.w);
    }

    float4 bv = ((const float4*)b)[lane];
    acc.x = fmaxf(fmaf(acc.x, dc, bv.x), 0.f);
    acc.y = fmaxf(fmaf(acc.y, dc, bv.y), 0.f);
    acc.z = fmaxf(fmaf(acc.z, dc, bv.z), 0.f);
    acc.w = fmaxf(fmaf(acc.w, dc, bv.w), 0.f);
    ((float4*)(out + (long)w * Hd))[lane] = acc;

    float4 pv = ((const float4*)p)[lane];
    float s = acc.x*pv.x + acc.y*pv.y + acc.z*pv.z + acc.w*pv.w;
#pragma unroll
    for (int o = 16; o; o >>= 1) s += __shfl_xor_sync(0xffffffffu, s, o);
    if (lane == 0) score[w] = s * __ldg(pinv);
}

// ------------------------------ p norms (all 3) -----------------------------
__global__ void pnorm3_k(const float* __restrict__ p1, const float* __restrict__ p2,
                         const float* __restrict__ p3) {   // <<<3,128>>>
    __shared__ float s[128];
    const float* p = (blockIdx.x == 0) ? p1 : (blockIdx.x == 1) ? p2 : p3;
    float v = p[threadIdx.x];
    s[threadIdx.x] = v * v;
    __syncthreads();
    for (int o = 64; o > 0; o >>= 1) {
        if (threadIdx.x < o) s[threadIdx.x] += s[threadIdx.x + o];
        __syncthreads();
    }
    if (threadIdx.x == 0) g_pinv[blockIdx.x] = rsqrtf(s[0]);
}

// ------- top-k (matches jax.lax.top_k) + readout + next-layer zeroing -------
__global__ void topk_k(const float* __restrict__ x, const float* __restrict__ score,
                       float* __restrict__ xs, int* __restrict__ newid,
                       int n_per, int k,
                       float* __restrict__ out, int addFlag,
                       int* __restrict__ cnt_next, int* __restrict__ cursor_next,
                       int* __restrict__ counter_next, int n_next) {
    __shared__ unsigned long long keys[1024];
    int g = blockIdx.x, t = threadIdx.x;
    int base = g * n_per;
    int gid = base + t;

    if (n_next > 0) {
        if (gid < n_next) { cnt_next[gid] = 0; cursor_next[gid] = 0; }
        if (gid == 0) *counter_next = 0;
    }

    newid[gid] = -1;
    float s = score[gid];
    unsigned int fb = __float_as_uint(s);
    unsigned int mp = (fb & 0x80000000u) ? ~fb : (fb | 0x80000000u);
    keys[t] = ((unsigned long long)(~mp) << 32) | (unsigned int)t;
    __syncthreads();

    for (int kk = 2; kk <= n_per; kk <<= 1) {
        for (int j = kk >> 1; j > 0; j >>= 1) {
            int ixj = t ^ j;
            if (ixj > t) {
                bool up = ((t & kk) == 0);
                unsigned long long a = keys[t], bq = keys[ixj];
                if ((a > bq) == up) { keys[t] = bq; keys[ixj] = a; }
            }
            __syncthreads();
        }
    }

    if (t < k) {
        int sel = (int)(keys[t] & 0xffffffffu);
        newid[base + sel] = g * k + t;
    }
    __syncthreads();

    int total = k * Hd;
    for (int idx = t; idx < total; idx += n_per) {
        int rank = idx >> 7, f = idx & 127;
        int sel = (int)(keys[rank] & 0xffffffffu);
        float tv = tanhf(score[base + sel]);
        xs[((long)(g * k + rank)) * Hd + f] = x[((long)(base + sel)) * Hd + f] * tv;
    }
    __syncthreads();

    if (t < 128) {
        const float* pr = xs + (long)g * k * Hd + t;
        float mx = -3.402823466e+38f, sm = 0.f;
        for (int r = 0; r < k; r++) {
            float v = pr[(long)r * Hd];
            mx = fmaxf(mx, v);
            sm += v;
        }
        float mean = sm / (float)k;
        if (addFlag) { out[g*256 + t] += mx; out[g*256 + 128 + t] += mean; }
        else         { out[g*256 + t]  = mx; out[g*256 + 128 + t]  = mean; }
    }
}

// ---- edge compaction (relabel + filter) + histogram of next layer ----------
__global__ void compact_k(const int* __restrict__ row, const int* __restrict__ col,
                          const int* __restrict__ newid,
                          int* __restrict__ orow, int* __restrict__ ocol,
                          int* __restrict__ cnt_next, int* __restrict__ counter,
                          const int* __restrict__ boundPtr, int maxE) {
    int e = blockIdx.x * blockDim.x + threadIdx.x;
    int bound = boundPtr ? __ldg(boundPtr) : maxE;
    bool valid = (e < bound);
    int nr = -1, nc = -1;
    if (valid) {
        nr = newid[row[e]];
        nc = newid[col[e]];
        valid = (nr >= 0) && (nc >= 0);
    }
    unsigned m = __ballot_sync(0xffffffffu, valid);
    if (valid) {
        int lane = threadIdx.x & 31;
        int leader = __ffs(m) - 1;
        int prefix = __popc(m & ((1u << lane) - 1u));
        int basep = 0;
        if (lane == leader) basep = atomicAdd(counter, __popc(m));
        basep = __shfl_sync(m, basep, leader);
        int pos = basep + prefix;
        orow[pos] = nr;
        ocol[pos] = nc;
        atomicAdd(&cnt_next[nc], 1);
    }
}

// ------------------------------- driver ------------------------------------
static inline int ceil_div(int a, int b) { return (a + b - 1) / b; }

struct Scratch {
    float *h, *cv, *xs1, *xs2, *xs3, *dinv, *sc, *pinv;
    int *nid, *cnt, *start, *cursor, *bsum, *src, *r0, *c0, *r1, *c1, *nE;
};

static void csr_and_conv(const Scratch& S, const float* xin, int n,
                         const int* erow, const int* ecol,
                         const int* boundPtr, int maxE,
                         const float* W, const float* b, const float* p, int layer)
{
    scanA_k<<<n / 1024, 1024>>>(S.cnt, S.start, S.bsum);
    scanB_k<<<1, 128>>>(S.bsum, n / 1024);
    scanC_k<<<ceil_div(n, 256), 256>>>(S.start, S.bsum, S.cnt, S.dinv, n);
    gemm128<<<n / 128, 512>>>(xin, W, S.h);
    fill_k<<<ceil_div(maxE, 256), 256>>>(erow, ecol, S.start, S.cursor, S.src,
                                         boundPtr, maxE);
    gather_k<<<ceil_div(n * 32, 256), 256>>>(S.h, S.start, S.cnt, S.src,
                                             S.dinv, b, p, S.pinv + layer,
                                             S.cv, S.sc, n);
}

extern "C" void kernel_launch(void* const* d_in, const int* in_sizes, int n_in,
                              void* d_out, int out_size)
{
    const float* x    = (const float*)d_in[0];
    const int*   erow = (const int*)  d_in[1];
    const int*   ecol = (const int*)  d_in[2];
    const float* W1 = (const float*)d_in[3],  *b1 = (const float*)d_in[4],  *p1 = (const float*)d_in[5];
    const float* W2 = (const float*)d_in[6],  *b2 = (const float*)d_in[7],  *p2 = (const float*)d_in[8];
    const float* W3 = (const float*)d_in[9],  *b3 = (const float*)d_in[10], *p3 = (const float*)d_in[11];
    float* out = (float*)d_out;
    const int E = in_sizes[1];

    Scratch S;
    cudaGetSymbolAddress((void**)&S.h,      g_h);
    cudaGetSymbolAddress((void**)&S.cv,     g_cv);
    cudaGetSymbolAddress((void**)&S.xs1,    g_xs1);
    cudaGetSymbolAddress((void**)&S.xs2,    g_xs2);
    cudaGetSymbolAddress((void**)&S.xs3,    g_xs3);
    cudaGetSymbolAddress((void**)&S.dinv,   g_dinv);
    cudaGetSymbolAddress((void**)&S.sc,     g_sc);
    cudaGetSymbolAddress((void**)&S.pinv,   g_pinv);
    cudaGetSymbolAddress((void**)&S.nid,    g_newid);
    cudaGetSymbolAddress((void**)&S.cnt,    g_cnt);
    cudaGetSymbolAddress((void**)&S.start,  g_start);
    cudaGetSymbolAddress((void**)&S.cursor, g_cursor);
    cudaGetSymbolAddress((void**)&S.bsum,   g_bsum);
    cudaGetSymbolAddress((void**)&S.src,    g_src);
    cudaGetSymbolAddress((void**)&S.r0,     g_r0);
    cudaGetSymbolAddress((void**)&S.c0,     g_c0);
    cudaGetSymbolAddress((void**)&S.r1,     g_r1);
    cudaGetSymbolAddress((void**)&S.c1,     g_c1);
    cudaGetSymbolAddress((void**)&S.nE,     g_nE);

    // ---------------- Layer 1: n=131072, keep 512/1024 ----------------
    // Launch order chosen so gemm128 is the 6th graph node (ncu -s 5 -c 1
    // profiles it next round).
    pnorm3_k<<<3, 128>>>(p1, p2, p3);                           // 1
    cudaMemsetAsync(S.cnt, 0, NN1 * sizeof(int));               // 2
    cudaMemsetAsync(S.cursor, 0, NN1 * sizeof(int));            // 3
    hist_k<<<ceil_div(E, 256), 256>>>(ecol, S.cnt, E);          // 4
    scanA_k<<<NN1 / 1024, 1024>>>(S.cnt, S.start, S.bsum);      // 5
    gemm128<<<NN1 / 128, 512>>>(x, W1, S.h);                    // 6  <- profiled
    scanB_k<<<1, 128>>>(S.bsum, NN1 / 1024);
    scanC_k<<<ceil_div(NN1, 256), 256>>>(S.start, S.bsum, S.cnt, S.dinv, NN1);
    fill_k<<<ceil_div(E, 256), 256>>>(erow, ecol, S.start, S.cursor, S.src,
                                      nullptr, E);
    gather_k<<<ceil_div(NN1 * 32, 256), 256>>>(S.h, S.start, S.cnt, S.src,
                                               S.dinv, b1, p1, S.pinv + 0,
                                               S.cv, S.sc, NN1);
    topk_k<<<Bg, 1024>>>(S.cv, S.sc, S.xs1, S.nid, 1024, 512, out, 0,
                         S.cnt, S.cursor, S.nE + 0, NN2);
    compact_k<<<ceil_div(E, 256), 256>>>(erow, ecol, S.nid, S.r0, S.c0,
                                         S.cnt, S.nE + 0, nullptr, E);

    // ---------------- Layer 2: n=65536, keep 256/512 ----------------
    csr_and_conv(S, S.xs1, NN2, S.r0, S.c0, S.nE + 0, E, W2, b2, p2, 1);
    topk_k<<<Bg, 512>>>(S.cv, S.sc, S.xs2, S.nid, 512, 256, out, 1,
                        S.cnt, S.cursor, S.nE + 1, NN3);
    compact_k<<<ceil_div(E, 256), 256>>>(S.r0, S.c0, S.nid, S.r1, S.c1,
                                         S.cnt, S.nE + 1, S.nE + 0, E);

    // ---------------- Layer 3: n=32768, keep 128/256 ----------------
    csr_and_conv(S, S.xs2, NN3, S.r1, S.c1, S.nE + 1, E, W3, b3, p3, 2);
    topk_k<<<Bg, 256>>>(S.cv, S.sc, S.xs3, S.nid, 256, 128, out, 1,
                        nullptr, nullptr, nullptr, 0);
}

// round 5
// speedup vs baseline: 1.2054x; 1.2054x over previous
#include <cuda_runtime.h>
#include <cuda_bf16.h>
#include <math.h>

// ---------------------------------------------------------------------------
// GCN + TopK pooling stack (3 layers), B=128 graphs, N=1024 nodes, H=128.
// ---------------------------------------------------------------------------

#define Bg   128
#define Npg  1024
#define Hd   128
#define NN1  (Bg*Npg)        // 131072
#define NN2  (Bg*512)        // 65536
#define NN3  (Bg*256)        // 32768
#define EMAX 1048576

// ------------------------- device scratch (no allocs) ----------------------
__device__ __align__(128) float g_h [NN1*Hd];   // h = (x @ W) * dinv[row]
__device__ __align__(128) float g_cv[NN1*Hd];   // conv output (relu'd)
__device__ __align__(128) float g_xs1[NN2*Hd];
__device__ __align__(128) float g_xs2[NN3*Hd];
__device__ __align__(128) float g_xs3[(Bg*128)*Hd];
__device__ float g_dinv[NN1];
__device__ float g_sc[NN1];
__device__ int   g_newid[NN1];
__device__ int   g_cnt[NN1];
__device__ int   g_start[NN1];
__device__ int   g_cursor[NN1];
__device__ int   g_bsum[256];
__device__ int   g_src[EMAX];
__device__ int   g_r0[EMAX], g_c0[EMAX];
__device__ int   g_r1[EMAX], g_c1[EMAX];
__device__ int   g_nE[2];
__device__ float g_pinv[3];

// ------------------------------ f32x2 helpers -------------------------------
__device__ __forceinline__ unsigned long long pack2(float x) {
    unsigned long long r;
    asm("mov.b64 %0, {%1, %1};" : "=l"(r) : "f"(x));
    return r;
}
__device__ __forceinline__ void fma2(unsigned long long& d,
                                     unsigned long long a, unsigned long long b) {
    asm("fma.rn.f32x2 %0, %1, %2, %0;" : "+l"(d) : "l"(a), "l"(b));
}

// ------------------------------- GEMM --------------------------------------
// Out[n,128] = (X[n,128] @ W[128,128]) * rsqrt(cnt[row]+1).
// 128-row tiles, 256 threads, 8x8 micro-tile.
// A staged in smem as DUPLICATED u64 pairs -> operands load directly via
// LDS.128 with no packing movs. B read as ulonglong2 from float smem.
#define KP 132

__global__ void __launch_bounds__(256, 2)
gemm128(const float* __restrict__ X, const float* __restrict__ W,
        const int* __restrict__ cnt, float* __restrict__ Out)
{
    __shared__ unsigned long long sXd[16][130];  // [k][row] duplicated
    __shared__ float sW[16][KP];                 // [k][col]
    const int tid = threadIdx.x;
    const int tx = tid & 15;       // 16 col groups of 8 cols
    const int ty = tid >> 4;       // 16 row groups of 8 rows
    const long row0 = (long)blockIdx.x * 128;

    unsigned long long acc[8][4];
#pragma unroll
    for (int i = 0; i < 8; i++)
#pragma unroll
        for (int j = 0; j < 4; j++) acc[i][j] = 0ull;

    for (int k0 = 0; k0 < 128; k0 += 16) {
        // stage W chunk: 512 float4, 2 per thread
#pragma unroll
        for (int q = 0; q < 2; q++) {
            int f = tid + q * 256;
            int kk = f >> 5, c4 = f & 31;
            float4 v = ((const float4*)(W + (k0 + kk) * 128))[c4];
            float* d = &sW[kk][c4 * 4];
            d[0] = v.x; d[1] = v.y; d[2] = v.z; d[3] = v.w;
        }
        // stage X chunk transposed + duplicated: 2 float4 per thread
#pragma unroll
        for (int q = 0; q < 2; q++) {
            int f = tid + q * 256;
            int r = f >> 2, kq = (f & 3) * 4;
            float4 v = ((const float4*)(X + (row0 + r) * 128 + k0))[f & 3];
            sXd[kq + 0][r] = pack2(v.x);
            sXd[kq + 1][r] = pack2(v.y);
            sXd[kq + 2][r] = pack2(v.z);
            sXd[kq + 3][r] = pack2(v.w);
        }
        __syncthreads();

#pragma unroll
        for (int k = 0; k < 16; k++) {
            const ulonglong2* bp = (const ulonglong2*)&sW[k][tx * 8];
            ulonglong2 b01 = bp[0];           // cols tx*8+0..3
            ulonglong2 b23 = bp[1];           // cols tx*8+4..7
            const ulonglong2* ap = (const ulonglong2*)&sXd[k][ty * 8];
            ulonglong2 a01 = ap[0], a23 = ap[1], a45 = ap[2], a67 = ap[3];
            unsigned long long av[8] = { a01.x, a01.y, a23.x, a23.y,
                                         a45.x, a45.y, a67.x, a67.y };
#pragma unroll
            for (int i = 0; i < 8; i++) {
                fma2(acc[i][0], av[i], b01.x);
                fma2(acc[i][1], av[i], b01.y);
                fma2(acc[i][2], av[i], b23.x);
                fma2(acc[i][3], av[i], b23.y);
            }
        }
        __syncthreads();
    }

#pragma unroll
    for (int i = 0; i < 8; i++) {
        long row = row0 + ty * 8 + i;
        float dv = rsqrtf((float)__ldg(&cnt[row]) + 1.0f);
        float* o = Out + row * 128 + tx * 8;
        float2 f0 = *(float2*)&acc[i][0];
        float2 f1 = *(float2*)&acc[i][1];
        float2 f2 = *(float2*)&acc[i][2];
        float2 f3 = *(float2*)&acc[i][3];
        *((float4*)o)       = make_float4(f0.x * dv, f0.y * dv, f1.x * dv, f1.y * dv);
        *((float4*)(o + 4)) = make_float4(f2.x * dv, f2.y * dv, f3.x * dv, f3.y * dv);
    }
}

// ------------------------- CSR build: hist / scan ---------------------------
__global__ void hist_k(const int* __restrict__ col, int* __restrict__ cnt, int nE) {
    int i = blockIdx.x * blockDim.x + threadIdx.x;
    if (i < nE) atomicAdd(&cnt[col[i]], 1);
}

__global__ void scanA_k(const int* __restrict__ cnt, int* __restrict__ start,
                        int* __restrict__ bsum) {
    __shared__ int s[1024];
    int t = threadIdx.x;
    int i = blockIdx.x * 1024 + t;
    int v = cnt[i];
    s[t] = v;
    __syncthreads();
    for (int o = 1; o < 1024; o <<= 1) {
        int add = (t >= o) ? s[t - o] : 0;
        __syncthreads();
        s[t] += add;
        __syncthreads();
    }
    start[i] = s[t] - v;
    if (t == 1023) bsum[blockIdx.x] = s[t];
}

__global__ void scanB_k(int* bsum, int nb) {   // <<<1,128>>>, nb <= 128
    __shared__ int s[128];
    int t = threadIdx.x;
    int v = (t < nb) ? bsum[t] : 0;
    s[t] = v;
    __syncthreads();
    for (int o = 1; o < 128; o <<= 1) {
        int add = (t >= o) ? s[t - o] : 0;
        __syncthreads();
        s[t] += add;
        __syncthreads();
    }
    if (t < nb) bsum[t] = s[t] - v;
}

__global__ void scanC_k(int* __restrict__ start, const int* __restrict__ bsum,
                        const int* __restrict__ cnt, float* __restrict__ dinv, int n) {
    int i = blockIdx.x * blockDim.x + threadIdx.x;
    if (i >= n) return;
    start[i] += bsum[i >> 10];
    dinv[i] = rsqrtf((float)cnt[i] + 1.0f);
}

__global__ void fill_k(const int* __restrict__ row, const int* __restrict__ col,
                       const int* __restrict__ start, int* __restrict__ cursor,
                       int* __restrict__ src, const int* __restrict__ boundPtr,
                       int maxE) {
    int i = blockIdx.x * blockDim.x + threadIdx.x;
    int bound = boundPtr ? __ldg(boundPtr) : maxE;
    if (i >= bound) return;
    int c = col[i];
    int p = atomicAdd(&cursor[c], 1);
    src[start[c] + p] = row[i];
}

// ---- gather (h is dinv-prescaled) + self + bias + relu + score, fused ------
__global__ void gather_k(const float* __restrict__ h, const int* __restrict__ start,
                         const int* __restrict__ cnt, const int* __restrict__ src,
                         const float* __restrict__ dinv, const float* __restrict__ b,
                         const float* __restrict__ p, const float* __restrict__ pinv,
                         float* __restrict__ out, float* __restrict__ score, int n) {
    int w = (blockIdx.x * blockDim.x + threadIdx.x) >> 5;
    if (w >= n) return;
    int lane = threadIdx.x & 31;
    float dc = dinv[w];
    int s0 = start[w], d = cnt[w];
    float4 acc = ((const float4*)(h + (long)w * Hd))[lane];  // self (prescaled)

    int e = 0;
    for (; e + 4 <= d; e += 4) {
        int r0 = __ldg(&src[s0 + e]);
        int r1 = __ldg(&src[s0 + e + 1]);
        int r2 = __ldg(&src[s0 + e + 2]);
        int r3 = __ldg(&src[s0 + e + 3]);
        float4 v0 = ((const float4*)(h + (long)r0 * Hd))[lane];
        float4 v1 = ((const float4*)(h + (long)r1 * Hd))[lane];
        float4 v2 = ((const float4*)(h + (long)r2 * Hd))[lane];
        float4 v3 = ((const float4*)(h + (long)r3 * Hd))[lane];
        acc.x += v0.x + v1.x + v2.x + v3.x;
        acc.y += v0.y + v1.y + v2.y + v3.y;
        acc.z += v0.z + v1.z + v2.z + v3.z;
        acc.w += v0.w + v1.w + v2.w + v3.w;
    }
    for (; e < d; e++) {
        int r = __ldg(&src[s0 + e]);
        float4 v = ((const float4*)(h + (long)r * Hd))[lane];
        acc.x += v.x; acc.y += v.y; acc.z += v.z; acc.w += v.w;
    }

    float4 bv = ((const float4*)b)[lane];
    acc.x = fmaxf(fmaf(acc.x, dc, bv.x), 0.f);
    acc.y = fmaxf(fmaf(acc.y, dc, bv.y), 0.f);
    acc.z = fmaxf(fmaf(acc.z, dc, bv.z), 0.f);
    acc.w = fmaxf(fmaf(acc.w, dc, bv.w), 0.f);
    ((float4*)(out + (long)w * Hd))[lane] = acc;

    float4 pv = ((const float4*)p)[lane];
    float s = acc.x*pv.x + acc.y*pv.y + acc.z*pv.z + acc.w*pv.w;
#pragma unroll
    for (int o = 16; o; o >>= 1) s += __shfl_xor_sync(0xffffffffu, s, o);
    if (lane == 0) score[w] = s * __ldg(pinv);
}

// ------------------------------ p norms (all 3) -----------------------------
__global__ void pnorm3_k(const float* __restrict__ p1, const float* __restrict__ p2,
                         const float* __restrict__ p3) {   // <<<3,128>>>
    __shared__ float s[128];
    const float* p = (blockIdx.x == 0) ? p1 : (blockIdx.x == 1) ? p2 : p3;
    float v = p[threadIdx.x];
    s[threadIdx.x] = v * v;
    __syncthreads();
    for (int o = 64; o > 0; o >>= 1) {
        if (threadIdx.x < o) s[threadIdx.x] += s[threadIdx.x + o];
        __syncthreads();
    }
    if (threadIdx.x == 0) g_pinv[blockIdx.x] = rsqrtf(s[0]);
}

// ------- top-k (matches jax.lax.top_k) + readout + next-layer zeroing -------
__global__ void topk_k(const float* __restrict__ x, const float* __restrict__ score,
                       float* __restrict__ xs, int* __restrict__ newid,
                       int n_per, int k,
                       float* __restrict__ out, int addFlag,
                       int* __restrict__ cnt_next, int* __restrict__ cursor_next,
                       int* __restrict__ counter_next, int n_next) {
    __shared__ unsigned long long keys[1024];
    int g = blockIdx.x, t = threadIdx.x;
    int base = g * n_per;
    int gid = base + t;

    if (n_next > 0) {
        if (gid < n_next) { cnt_next[gid] = 0; cursor_next[gid] = 0; }
        if (gid == 0) *counter_next = 0;
    }

    newid[gid] = -1;
    float s = score[gid];
    unsigned int fb = __float_as_uint(s);
    unsigned int mp = (fb & 0x80000000u) ? ~fb : (fb | 0x80000000u);
    keys[t] = ((unsigned long long)(~mp) << 32) | (unsigned int)t;
    __syncthreads();

    for (int kk = 2; kk <= n_per; kk <<= 1) {
        for (int j = kk >> 1; j > 0; j >>= 1) {
            int ixj = t ^ j;
            if (ixj > t) {
                bool up = ((t & kk) == 0);
                unsigned long long a = keys[t], bq = keys[ixj];
                if ((a > bq) == up) { keys[t] = bq; keys[ixj] = a; }
            }
            __syncthreads();
        }
    }

    if (t < k) {
        int sel = (int)(keys[t] & 0xffffffffu);
        newid[base + sel] = g * k + t;
    }
    __syncthreads();

    int total = k * Hd;
    for (int idx = t; idx < total; idx += n_per) {
        int rank = idx >> 7, f = idx & 127;
        int sel = (int)(keys[rank] & 0xffffffffu);
        float tv = tanhf(score[base + sel]);
        xs[((long)(g * k + rank)) * Hd + f] = x[((long)(base + sel)) * Hd + f] * tv;
    }
    __syncthreads();

    if (t < 128) {
        const float* pr = xs + (long)g * k * Hd + t;
        float mx = -3.402823466e+38f, sm = 0.f;
        for (int r = 0; r < k; r++) {
            float v = pr[(long)r * Hd];
            mx = fmaxf(mx, v);
            sm += v;
        }
        float mean = sm / (float)k;
        if (addFlag) { out[g*256 + t] += mx; out[g*256 + 128 + t] += mean; }
        else         { out[g*256 + t]  = mx; out[g*256 + 128 + t]  = mean; }
    }
}

// ---- edge compaction (relabel + filter) + histogram of next layer ----------
__global__ void compact_k(const int* __restrict__ row, const int* __restrict__ col,
                          const int* __restrict__ newid,
                          int* __restrict__ orow, int* __restrict__ ocol,
                          int* __restrict__ cnt_next, int* __restrict__ counter,
                          const int* __restrict__ boundPtr, int maxE) {
    int e = blockIdx.x * blockDim.x + threadIdx.x;
    int bound = boundPtr ? __ldg(boundPtr) : maxE;
    bool valid = (e < bound);
    int nr = -1, nc = -1;
    if (valid) {
        nr = newid[row[e]];
        nc = newid[col[e]];
        valid = (nr >= 0) && (nc >= 0);
    }
    unsigned m = __ballot_sync(0xffffffffu, valid);
    if (valid) {
        int lane = threadIdx.x & 31;
        int leader = __ffs(m) - 1;
        int prefix = __popc(m & ((1u << lane) - 1u));
        int basep = 0;
        if (lane == leader) basep = atomicAdd(counter, __popc(m));
        basep = __shfl_sync(m, basep, leader);
        int pos = basep + prefix;
        orow[pos] = nr;
        ocol[pos] = nc;
        atomicAdd(&cnt_next[nc], 1);
    }
}

// ------------------------------- driver ------------------------------------
static inline int ceil_div(int a, int b) { return (a + b - 1) / b; }

struct Scratch {
    float *h, *cv, *xs1, *xs2, *xs3, *dinv, *sc, *pinv;
    int *nid, *cnt, *start, *cursor, *bsum, *src, *r0, *c0, *r1, *c1, *nE;
};

static void csr_and_conv(const Scratch& S, const float* xin, int n,
                         const int* erow, const int* ecol,
                         const int* boundPtr, int maxE,
                         const float* W, const float* b, const float* p, int layer)
{
    gemm128<<<n / 128, 256>>>(xin, W, S.cnt, S.h);
    scanA_k<<<n / 1024, 1024>>>(S.cnt, S.start, S.bsum);
    scanB_k<<<1, 128>>>(S.bsum, n / 1024);
    scanC_k<<<ceil_div(n, 256), 256>>>(S.start, S.bsum, S.cnt, S.dinv, n);
    fill_k<<<ceil_div(maxE, 256), 256>>>(erow, ecol, S.start, S.cursor, S.src,
                                         boundPtr, maxE);
    gather_k<<<ceil_div(n * 32, 256), 256>>>(S.h, S.start, S.cnt, S.src,
                                             S.dinv, b, p, S.pinv + layer,
                                             S.cv, S.sc, n);
}

extern "C" void kernel_launch(void* const* d_in, const int* in_sizes, int n_in,
                              void* d_out, int out_size)
{
    const float* x    = (const float*)d_in[0];
    const int*   erow = (const int*)  d_in[1];
    const int*   ecol = (const int*)  d_in[2];
    const float* W1 = (const float*)d_in[3],  *b1 = (const float*)d_in[4],  *p1 = (const float*)d_in[5];
    const float* W2 = (const float*)d_in[6],  *b2 = (const float*)d_in[7],  *p2 = (const float*)d_in[8];
    const float* W3 = (const float*)d_in[9],  *b3 = (const float*)d_in[10], *p3 = (const float*)d_in[11];
    float* out = (float*)d_out;
    const int E = in_sizes[1];

    Scratch S;
    cudaGetSymbolAddress((void**)&S.h,      g_h);
    cudaGetSymbolAddress((void**)&S.cv,     g_cv);
    cudaGetSymbolAddress((void**)&S.xs1,    g_xs1);
    cudaGetSymbolAddress((void**)&S.xs2,    g_xs2);
    cudaGetSymbolAddress((void**)&S.xs3,    g_xs3);
    cudaGetSymbolAddress((void**)&S.dinv,   g_dinv);
    cudaGetSymbolAddress((void**)&S.sc,     g_sc);
    cudaGetSymbolAddress((void**)&S.pinv,   g_pinv);
    cudaGetSymbolAddress((void**)&S.nid,    g_newid);
    cudaGetSymbolAddress((void**)&S.cnt,    g_cnt);
    cudaGetSymbolAddress((void**)&S.start,  g_start);
    cudaGetSymbolAddress((void**)&S.cursor, g_cursor);
    cudaGetSymbolAddress((void**)&S.bsum,   g_bsum);
    cudaGetSymbolAddress((void**)&S.src,    g_src);
    cudaGetSymbolAddress((void**)&S.r0,     g_r0);
    cudaGetSymbolAddress((void**)&S.c0,     g_c0);
    cudaGetSymbolAddress((void**)&S.r1,     g_r1);
    cudaGetSymbolAddress((void**)&S.c1,     g_c1);
    cudaGetSymbolAddress((void**)&S.nE,     g_nE);

    // ---------------- Layer 1: n=131072, keep 512/1024 ----------------
    // gemm128 is the 6th graph node (ncu -s 5 -c 1 profiles it).
    pnorm3_k<<<3, 128>>>(p1, p2, p3);                           // 1
    cudaMemsetAsync(S.cnt, 0, NN1 * sizeof(int));               // 2
    cudaMemsetAsync(S.cursor, 0, NN1 * sizeof(int));            // 3
    hist_k<<<ceil_div(E, 256), 256>>>(ecol, S.cnt, E);          // 4
    scanA_k<<<NN1 / 1024, 1024>>>(S.cnt, S.start, S.bsum);      // 5
    gemm128<<<NN1 / 128, 256>>>(x, W1, S.cnt, S.h);             // 6  <- profiled
    scanB_k<<<1, 128>>>(S.bsum, NN1 / 1024);
    scanC_k<<<ceil_div(NN1, 256), 256>>>(S.start, S.bsum, S.cnt, S.dinv, NN1);
    fill_k<<<ceil_div(E, 256), 256>>>(erow, ecol, S.start, S.cursor, S.src,
                                      nullptr, E);
    gather_k<<<ceil_div(NN1 * 32, 256), 256>>>(S.h, S.start, S.cnt, S.src,
                                               S.dinv, b1, p1, S.pinv + 0,
                                               S.cv, S.sc, NN1);
    topk_k<<<Bg, 1024>>>(S.cv, S.sc, S.xs1, S.nid, 1024, 512, out, 0,
                         S.cnt, S.cursor, S.nE + 0, NN2);
    compact_k<<<ceil_div(E, 256), 256>>>(erow, ecol, S.nid, S.r0, S.c0,
                                         S.cnt, S.nE + 0, nullptr, E);

    // ---------------- Layer 2: n=65536, keep 256/512 ----------------
    csr_and_conv(S, S.xs1, NN2, S.r0, S.c0, S.nE + 0, E, W2, b2, p2, 1);
    topk_k<<<Bg, 512>>>(S.cv, S.sc, S.xs2, S.nid, 512, 256, out, 1,
                        S.cnt, S.cursor, S.nE + 1, NN3);
    compact_k<<<ceil_div(E, 256), 256>>>(S.r0, S.c0, S.nid, S.r1, S.c1,
                                         S.cnt, S.nE + 1, S.nE + 0, E);

    // ---------------- Layer 3: n=32768, keep 128/256 ----------------
    csr_and_conv(S, S.xs2, NN3, S.r1, S.c1, S.nE + 1, E, W3, b3, p3, 2);
    topk_k<<<Bg, 256>>>(S.cv, S.sc, S.xs3, S.nid, 256, 128, out, 1,
                        nullptr, nullptr, nullptr, 0);
}

// round 9
// speedup vs baseline: 1.3398x; 1.1115x over previous
#include <cuda_runtime.h>
#include <cuda_bf16.h>
#include <cstdint>
#include <math.h>

// ---------------------------------------------------------------------------
// GCN + TopK pooling stack (3 layers), B=128 graphs, N=1024 nodes, H=128.
// GEMM on tensor cores via mma.sync m16n8k8 tf32, 3-term split (fp32-accurate).
// ---------------------------------------------------------------------------

#define Bg   128
#define Npg  1024
#define Hd   128
#define NN1  (Bg*Npg)        // 131072
#define NN2  (Bg*512)        // 65536
#define NN3  (Bg*256)        // 32768
#define EMAX 1048576

// ------------------------- device scratch (no allocs) ----------------------
__device__ __align__(128) float g_h [NN1*Hd];   // h = (x @ W) * dinv[row]
__device__ __align__(128) float g_cv[NN1*Hd];   // conv output (relu'd)
__device__ __align__(128) float g_xs1[NN2*Hd];
__device__ __align__(128) float g_xs2[NN3*Hd];
__device__ __align__(128) float g_xs3[(Bg*128)*Hd];
__device__ __align__(16) float g_bfh[3*16384];  // W hi split, fragment order
__device__ __align__(16) float g_bfl[3*16384];  // W lo split, fragment order
__device__ float g_dinv[NN1];
__device__ float g_sc[NN1];
__device__ int   g_newid[NN1];
__device__ int   g_cnt[NN1];
__device__ int   g_start[NN1];
__device__ int   g_cursor[NN1];
__device__ int   g_bsum[256];
__device__ int   g_src[EMAX];
__device__ int   g_r0[EMAX], g_c0[EMAX];
__device__ int   g_r1[EMAX], g_c1[EMAX];
__device__ int   g_nE[2];
__device__ float g_pinv[3];

// --------------------------- helpers ----------------------------------------
__device__ __forceinline__ float tf32r(float v) {
    float h;
    asm("cvt.rna.tf32.f32 %0, %1;" : "=f"(h) : "f"(v));
    return h;
}

__device__ __forceinline__ void mma8(float* c, const float4 a, const float2 b) {
    asm volatile(
        "mma.sync.aligned.m16n8k8.row.col.f32.tf32.tf32.f32 "
        "{%0,%1,%2,%3}, {%4,%5,%6,%7}, {%8,%9}, {%0,%1,%2,%3};"
        : "+f"(c[0]), "+f"(c[1]), "+f"(c[2]), "+f"(c[3])
        : "r"(__float_as_uint(a.x)), "r"(__float_as_uint(a.y)),
          "r"(__float_as_uint(a.z)), "r"(__float_as_uint(a.w)),
          "r"(__float_as_uint(b.x)), "r"(__float_as_uint(b.y)));
}

// -------- W -> fragment-order tf32 hi/lo tensors (once per run) --------------
// Layout per layer: [kc(4)][nt(16)][ks(4)][lane(32)][2]  (16384 floats)
// b0: k = kc*32+ks*8+(l&3),   n = nt*8+(l>>2)
// b1: k = +4, same n
__global__ void wsplit_k(const float* __restrict__ W1, const float* __restrict__ W2,
                         const float* __restrict__ W3,
                         float* __restrict__ bfh, float* __restrict__ bfl) {
    int layer = blockIdx.x >> 7;          // grid = 384, block = 128
    int idx = (blockIdx.x & 127) * 128 + threadIdx.x;   // 0..16383
    const float* W = (layer == 0) ? W1 : (layer == 1) ? W2 : W3;
    int j  = idx & 1;
    int l  = (idx >> 1) & 31;
    int ks = (idx >> 6) & 3;
    int nt = (idx >> 8) & 15;
    int kc = idx >> 12;
    int k = kc * 32 + ks * 8 + (l & 3) + (j << 2);
    int n = nt * 8 + (l >> 2);
    float v = W[k * 128 + n];
    float h = tf32r(v);
    bfh[layer * 16384 + idx] = h;
    bfl[layer * 16384 + idx] = v - h;
}

// --------------------------- mma.sync GEMM ----------------------------------
// Out[row0+r][n] = sum_k X[r,k]*W[k,n] * rsqrt(cnt[row]+1).
// 128-row tile, 8 warps; warp w owns m-tile w (16 rows) x 128 cols.
__global__ void __launch_bounds__(256, 2)
gemm_mma(const float* __restrict__ X, const float* __restrict__ Bfh,
         const float* __restrict__ Bfl, const int* __restrict__ cnt,
         float* __restrict__ Out)
{
    __shared__ float Ah[8*4*32*4];   // [mt][ks][lane][4]  16KB
    __shared__ float Al[8*4*32*4];   // 16KB
    __shared__ float Bh[16*4*32*2];  // [nt][ks][lane][2]  8KB
    __shared__ float Bl[16*4*32*2];  // 8KB
    const int tid = threadIdx.x;
    const int w = tid >> 5, l = tid & 31;
    const long row0 = (long)blockIdx.x * 128;

    float acc[16][4];
#pragma unroll
    for (int nt = 0; nt < 16; nt++)
#pragma unroll
        for (int j = 0; j < 4; j++) acc[nt][j] = 0.f;

    for (int kc = 0; kc < 4; kc++) {
        __syncthreads();               // previous chunk's compute done
        // stage A fragments (hi/lo split): 4 frags per thread
#pragma unroll
        for (int i = 0; i < 4; i++) {
            int f = tid + i * 256;                 // 0..1023
            int fl = f & 31, ks = (f >> 5) & 3, mt = f >> 7;
            long row = row0 + mt * 16 + (fl >> 2);
            int k = kc * 32 + ks * 8 + (fl & 3);
            float v0 = X[row * 128 + k];
            float v1 = X[(row + 8) * 128 + k];
            float v2 = X[row * 128 + k + 4];
            float v3 = X[(row + 8) * 128 + k + 4];
            float h0 = tf32r(v0), h1 = tf32r(v1), h2 = tf32r(v2), h3 = tf32r(v3);
            int o = f * 4;
            *(float4*)&Ah[o] = make_float4(h0, h1, h2, h3);
            *(float4*)&Al[o] = make_float4(v0 - h0, v1 - h1, v2 - h2, v3 - h3);
        }
        // stage B fragments: straight float4 copies (pre-fragmented in global)
        const float4* sbh = (const float4*)(Bfh + kc * 4096);
        const float4* sbl = (const float4*)(Bfl + kc * 4096);
#pragma unroll
        for (int i = 0; i < 4; i++) {
            int f = tid + i * 256;                 // 0..1023 float4s
            ((float4*)Bh)[f] = sbh[f];
            ((float4*)Bl)[f] = sbl[f];
        }
        __syncthreads();

#pragma unroll
        for (int ks = 0; ks < 4; ks++) {
            float4 ah = *(const float4*)&Ah[((w * 4 + ks) * 32 + l) * 4];
            float4 al = *(const float4*)&Al[((w * 4 + ks) * 32 + l) * 4];
#pragma unroll
            for (int nt = 0; nt < 16; nt++) {
                float2 bh = *(const float2*)&Bh[((nt * 4 + ks) * 32 + l) * 2];
                float2 bl = *(const float2*)&Bl[((nt * 4 + ks) * 32 + l) * 2];
                mma8(acc[nt], ah, bh);
                mma8(acc[nt], ah, bl);
                mma8(acc[nt], al, bh);
            }
        }
    }

    // epilogue: c0 at (row=l>>2, col=nt*8+(l&3)*2), c1 col+1, c2/c3 row+8
    int r0 = (int)row0 + w * 16 + (l >> 2);
    float dv0 = rsqrtf((float)__ldg(&cnt[r0]) + 1.0f);
    float dv1 = rsqrtf((float)__ldg(&cnt[r0 + 8]) + 1.0f);
#pragma unroll
    for (int nt = 0; nt < 16; nt++) {
        int col = nt * 8 + (l & 3) * 2;
        *(float2*)&Out[(long)r0 * 128 + col] =
            make_float2(acc[nt][0] * dv0, acc[nt][1] * dv0);
        *(float2*)&Out[(long)(r0 + 8) * 128 + col] =
            make_float2(acc[nt][2] * dv1, acc[nt][3] * dv1);
    }
}

// ------------------------- CSR build: hist / scan ---------------------------
__global__ void hist_k(const int* __restrict__ col, int* __restrict__ cnt, int nE) {
    int i = blockIdx.x * blockDim.x + threadIdx.x;
    if (i < nE) atomicAdd(&cnt[col[i]], 1);
}

__global__ void scanA_k(const int* __restrict__ cnt, int* __restrict__ start,
                        int* __restrict__ bsum) {
    __shared__ int s[1024];
    int t = threadIdx.x;
    int i = blockIdx.x * 1024 + t;
    int v = cnt[i];
    s[t] = v;
    __syncthreads();
    for (int o = 1; o < 1024; o <<= 1) {
        int add = (t >= o) ? s[t - o] : 0;
        __syncthreads();
        s[t] += add;
        __syncthreads();
    }
    start[i] = s[t] - v;
    if (t == 1023) bsum[blockIdx.x] = s[t];
}

__global__ void scanB_k(int* bsum, int nb) {   // <<<1,128>>>, nb <= 128
    __shared__ int s[128];
    int t = threadIdx.x;
    int v = (t < nb) ? bsum[t] : 0;
    s[t] = v;
    __syncthreads();
    for (int o = 1; o < 128; o <<= 1) {
        int add = (t >= o) ? s[t - o] : 0;
        __syncthreads();
        s[t] += add;
        __syncthreads();
    }
    if (t < nb) bsum[t] = s[t] - v;
}

__global__ void scanC_k(int* __restrict__ start, const int* __restrict__ bsum,
                        const int* __restrict__ cnt, float* __restrict__ dinv, int n) {
    int i = blockIdx.x * blockDim.x + threadIdx.x;
    if (i >= n) return;
    start[i] += bsum[i >> 10];
    dinv[i] = rsqrtf((float)cnt[i] + 1.0f);
}

__global__ void fill_k(const int* __restrict__ row, const int* __restrict__ col,
                       const int* __restrict__ start, int* __restrict__ cursor,
                       int* __restrict__ src, const int* __restrict__ boundPtr,
                       int maxE) {
    int i = blockIdx.x * blockDim.x + threadIdx.x;
    int bound = boundPtr ? __ldg(boundPtr) : maxE;
    if (i >= bound) return;
    int c = col[i];
    int p = atomicAdd(&cursor[c], 1);
    src[start[c] + p] = row[i];
}

// ---- gather (h is dinv-prescaled) + self + bias + relu + score, fused ------
__global__ void gather_k(const float* __restrict__ h, const int* __restrict__ start,
                         const int* __restrict__ cnt, const int* __restrict__ src,
                         const float* __restrict__ dinv, const float* __restrict__ b,
                         const float* __restrict__ p, const float* __restrict__ pinv,
                         float* __restrict__ out, float* __restrict__ score, int n) {
    int w = (blockIdx.x * blockDim.x + threadIdx.x) >> 5;
    if (w >= n) return;
    int lane = threadIdx.x & 31;
    float dc = dinv[w];
    int s0 = start[w], d = cnt[w];
    float4 acc = ((const float4*)(h + (long)w * Hd))[lane];  // self (prescaled)

    int e = 0;
    for (; e + 4 <= d; e += 4) {
        int r0 = __ldg(&src[s0 + e]);
        int r1 = __ldg(&src[s0 + e + 1]);
        int r2 = __ldg(&src[s0 + e + 2]);
        int r3 = __ldg(&src[s0 + e + 3]);
        float4 v0 = ((const float4*)(h + (long)r0 * Hd))[lane];
        float4 v1 = ((const float4*)(h + (long)r1 * Hd))[lane];
        float4 v2 = ((const float4*)(h + (long)r2 * Hd))[lane];
        float4 v3 = ((const float4*)(h + (long)r3 * Hd))[lane];
        acc.x += v0.x + v1.x + v2.x + v3.x;
        acc.y += v0.y + v1.y + v2.y + v3.y;
        acc.z += v0.z + v1.z + v2.z + v3.z;
        acc.w += v0.w + v1.w + v2.w + v3.w;
    }
    for (; e < d; e++) {
        int r = __ldg(&src[s0 + e]);
        float4 v = ((const float4*)(h + (long)r * Hd))[lane];
        acc.x += v.x; acc.y += v.y; acc.z += v.z; acc.w += v.w;
    }

    float4 bv = ((const float4*)b)[lane];
    acc.x = fmaxf(fmaf(acc.x, dc, bv.x), 0.f);
    acc.y = fmaxf(fmaf(acc.y, dc, bv.y), 0.f);
    acc.z = fmaxf(fmaf(acc.z, dc, bv.z), 0.f);
    acc.w = fmaxf(fmaf(acc.w, dc, bv.w), 0.f);
    ((float4*)(out + (long)w * Hd))[lane] = acc;

    float4 pv = ((const float4*)p)[lane];
    float s = acc.x*pv.x + acc.y*pv.y + acc.z*pv.z + acc.w*pv.w;
#pragma unroll
    for (int o = 16; o; o >>= 1) s += __shfl_xor_sync(0xffffffffu, s, o);
    if (lane == 0) score[w] = s * __ldg(pinv);
}

// ------------------------------ p norms (all 3) -----------------------------
__global__ void pnorm3_k(const float* __restrict__ p1, const float* __restrict__ p2,
                         const float* __restrict__ p3) {   // <<<3,128>>>
    __shared__ float s[128];
    const float* p = (blockIdx.x == 0) ? p1 : (blockIdx.x == 1) ? p2 : p3;
    float v = p[threadIdx.x];
    s[threadIdx.x] = v * v;
    __syncthreads();
    for (int o = 64; o > 0; o >>= 1) {
        if (threadIdx.x < o) s[threadIdx.x] += s[threadIdx.x + o];
        __syncthreads();
    }
    if (threadIdx.x == 0) g_pinv[blockIdx.x] = rsqrtf(s[0]);
}

// ------- top-k (matches jax.lax.top_k) + readout + next-layer zeroing -------
__global__ void topk_k(const float* __restrict__ x, const float* __restrict__ score,
                       float* __restrict__ xs, int* __restrict__ newid,
                       int n_per, int k,
                       float* __restrict__ out, int addFlag,
                       int* __restrict__ cnt_next, int* __restrict__ cursor_next,
                       int* __restrict__ counter_next, int n_next) {
    __shared__ unsigned long long keys[1024];
    int g = blockIdx.x, t = threadIdx.x;
    int base = g * n_per;
    int gid = base + t;

    if (n_next > 0) {
        if (gid < n_next) { cnt_next[gid] = 0; cursor_next[gid] = 0; }
        if (gid == 0) *counter_next = 0;
    }

    newid[gid] = -1;
    float s = score[gid];
    unsigned int fb = __float_as_uint(s);
    unsigned int mp = (fb & 0x80000000u) ? ~fb : (fb | 0x80000000u);
    keys[t] = ((unsigned long long)(~mp) << 32) | (unsigned int)t;
    __syncthreads();

    for (int kk = 2; kk <= n_per; kk <<= 1) {
        for (int j = kk >> 1; j > 0; j >>= 1) {
            int ixj = t ^ j;
            if (ixj > t) {
                bool up = ((t & kk) == 0);
                unsigned long long a = keys[t], bq = keys[ixj];
                if ((a > bq) == up) { keys[t] = bq; keys[ixj] = a; }
            }
            __syncthreads();
        }
    }

    if (t < k) {
        int sel = (int)(keys[t] & 0xffffffffu);
        newid[base + sel] = g * k + t;
    }
    __syncthreads();

    int total = k * Hd;
    for (int idx = t; idx < total; idx += n_per) {
        int rank = idx >> 7, f = idx & 127;
        int sel = (int)(keys[rank] & 0xffffffffu);
        float tv = tanhf(score[base + sel]);
        xs[((long)(g * k + rank)) * Hd + f] = x[((long)(base + sel)) * Hd + f] * tv;
    }
    __syncthreads();

    if (t < 128) {
        const float* pr = xs + (long)g * k * Hd + t;
        float mx = -3.402823466e+38f, sm = 0.f;
        for (int r = 0; r < k; r++) {
            float v = pr[(long)r * Hd];
            mx = fmaxf(mx, v);
            sm += v;
        }
        float mean = sm / (float)k;
        if (addFlag) { out[g*256 + t] += mx; out[g*256 + 128 + t] += mean; }
        else         { out[g*256 + t]  = mx; out[g*256 + 128 + t]  = mean; }
    }
}

// ---- edge compaction (relabel + filter) + histogram of next layer ----------
__global__ void compact_k(const int* __restrict__ row, const int* __restrict__ col,
                          const int* __restrict__ newid,
                          int* __restrict__ orow, int* __restrict__ ocol,
                          int* __restrict__ cnt_next, int* __restrict__ counter,
                          const int* __restrict__ boundPtr, int maxE) {
    int e = blockIdx.x * blockDim.x + threadIdx.x;
    int bound = boundPtr ? __ldg(boundPtr) : maxE;
    bool valid = (e < bound);
    int nr = -1, nc = -1;
    if (valid) {
        nr = newid[row[e]];
        nc = newid[col[e]];
        valid = (nr >= 0) && (nc >= 0);
    }
    unsigned m = __ballot_sync(0xffffffffu, valid);
    if (valid) {
        int lane = threadIdx.x & 31;
        int leader = __ffs(m) - 1;
        int prefix = __popc(m & ((1u << lane) - 1u));
        int basep = 0;
        if (lane == leader) basep = atomicAdd(counter, __popc(m));
        basep = __shfl_sync(m, basep, leader);
        int pos = basep + prefix;
        orow[pos] = nr;
        ocol[pos] = nc;
        atomicAdd(&cnt_next[nc], 1);
    }
}

// ------------------------------- driver ------------------------------------
static inline int ceil_div(int a, int b) { return (a + b - 1) / b; }

struct Scratch {
    float *h, *cv, *xs1, *xs2, *xs3, *dinv, *sc, *pinv, *bfh, *bfl;
    int *nid, *cnt, *start, *cursor, *bsum, *src, *r0, *c0, *r1, *c1, *nE;
};

static void csr_and_conv(const Scratch& S, const float* xin, int n,
                         const int* erow, const int* ecol,
                         const int* boundPtr, int maxE,
                         int layer, const float* b, const float* p)
{
    gemm_mma<<<n / 128, 256>>>(xin, S.bfh + layer * 16384,
                               S.bfl + layer * 16384, S.cnt, S.h);
    scanA_k<<<n / 1024, 1024>>>(S.cnt, S.start, S.bsum);
    scanB_k<<<1, 128>>>(S.bsum, n / 1024);
    scanC_k<<<ceil_div(n, 256), 256>>>(S.start, S.bsum, S.cnt, S.dinv, n);
    fill_k<<<ceil_div(maxE, 256), 256>>>(erow, ecol, S.start, S.cursor, S.src,
                                         boundPtr, maxE);
    gather_k<<<ceil_div(n * 32, 256), 256>>>(S.h, S.start, S.cnt, S.src,
                                             S.dinv, b, p, S.pinv + layer,
                                             S.cv, S.sc, n);
}

extern "C" void kernel_launch(void* const* d_in, const int* in_sizes, int n_in,
                              void* d_out, int out_size)
{
    const float* x    = (const float*)d_in[0];
    const int*   erow = (const int*)  d_in[1];
    const int*   ecol = (const int*)  d_in[2];
    const float* W1 = (const float*)d_in[3],  *b1 = (const float*)d_in[4],  *p1 = (const float*)d_in[5];
    const float* W2 = (const float*)d_in[6],  *b2 = (const float*)d_in[7],  *p2 = (const float*)d_in[8];
    const float* W3 = (const float*)d_in[9],  *b3 = (const float*)d_in[10], *p3 = (const float*)d_in[11];
    float* out = (float*)d_out;
    const int E = in_sizes[1];

    Scratch S;
    cudaGetSymbolAddress((void**)&S.h,      g_h);
    cudaGetSymbolAddress((void**)&S.cv,     g_cv);
    cudaGetSymbolAddress((void**)&S.xs1,    g_xs1);
    cudaGetSymbolAddress((void**)&S.xs2,    g_xs2);
    cudaGetSymbolAddress((void**)&S.xs3,    g_xs3);
    cudaGetSymbolAddress((void**)&S.bfh,    g_bfh);
    cudaGetSymbolAddress((void**)&S.bfl,    g_bfl);
    cudaGetSymbolAddress((void**)&S.dinv,   g_dinv);
    cudaGetSymbolAddress((void**)&S.sc,     g_sc);
    cudaGetSymbolAddress((void**)&S.pinv,   g_pinv);
    cudaGetSymbolAddress((void**)&S.nid,    g_newid);
    cudaGetSymbolAddress((void**)&S.cnt,    g_cnt);
    cudaGetSymbolAddress((void**)&S.start,  g_start);
    cudaGetSymbolAddress((void**)&S.cursor, g_cursor);
    cudaGetSymbolAddress((void**)&S.bsum,   g_bsum);
    cudaGetSymbolAddress((void**)&S.src,    g_src);
    cudaGetSymbolAddress((void**)&S.r0,     g_r0);
    cudaGetSymbolAddress((void**)&S.c0,     g_c0);
    cudaGetSymbolAddress((void**)&S.r1,     g_r1);
    cudaGetSymbolAddress((void**)&S.c1,     g_c1);
    cudaGetSymbolAddress((void**)&S.nE,     g_nE);

    // ---------------- Layer 1: n=131072, keep 512/1024 ----------------
    // gemm_mma is the 6th graph node (ncu -s 5 -c 1 profiles it).
    wsplit_k<<<384, 128>>>(W1, W2, W3, S.bfh, S.bfl);            // 1
    cudaMemsetAsync(S.cnt, 0, NN1 * sizeof(int));                // 2
    cudaMemsetAsync(S.cursor, 0, NN1 * sizeof(int));             // 3
    hist_k<<<ceil_div(E, 256), 256>>>(ecol, S.cnt, E);           // 4
    scanA_k<<<NN1 / 1024, 1024>>>(S.cnt, S.start, S.bsum);       // 5
    gemm_mma<<<NN1 / 128, 256>>>(x, S.bfh, S.bfl, S.cnt, S.h);   // 6  <- profiled
    pnorm3_k<<<3, 128>>>(p1, p2, p3);
    scanB_k<<<1, 128>>>(S.bsum, NN1 / 1024);
    scanC_k<<<ceil_div(NN1, 256), 256>>>(S.start, S.bsum, S.cnt, S.dinv, NN1);
    fill_k<<<ceil_div(E, 256), 256>>>(erow, ecol, S.start, S.cursor, S.src,
                                      nullptr, E);
    gather_k<<<ceil_div(NN1 * 32, 256), 256>>>(S.h, S.start, S.cnt, S.src,
                                               S.dinv, b1, p1, S.pinv + 0,
                                               S.cv, S.sc, NN1);
    topk_k<<<Bg, 1024>>>(S.cv, S.sc, S.xs1, S.nid, 1024, 512, out, 0,
                         S.cnt, S.cursor, S.nE + 0, NN2);
    compact_k<<<ceil_div(E, 256), 256>>>(erow, ecol, S.nid, S.r0, S.c0,
                                         S.cnt, S.nE + 0, nullptr, E);

    // ---------------- Layer 2: n=65536, keep 256/512 ----------------
    csr_and_conv(S, S.xs1, NN2, S.r0, S.c0, S.nE + 0, E, 1, b2, p2);
    topk_k<<<Bg, 512>>>(S.cv, S.sc, S.xs2, S.nid, 512, 256, out, 1,
                        S.cnt, S.cursor, S.nE + 1, NN3);
    compact_k<<<ceil_div(E, 256), 256>>>(S.r0, S.c0, S.nid, S.r1, S.c1,
                                         S.cnt, S.nE + 1, S.nE + 0, E);

    // ---------------- Layer 3: n=32768, keep 128/256 ----------------
    csr_and_conv(S, S.xs2, NN3, S.r1, S.c1, S.nE + 1, E, 2, b3, p3);
    topk_k<<<Bg, 256>>>(S.cv, S.sc, S.xs3, S.nid, 256, 128, out, 1,
                        nullptr, nullptr, nullptr, 0);
}

// round 11
// speedup vs baseline: 1.3481x; 1.0062x over previous
#include <cuda_runtime.h>
#include <cuda_bf16.h>
#include <cstdint>
#include <math.h>

// ---------------------------------------------------------------------------
// GCN + TopK pooling stack (3 layers), B=128 graphs, N=1024 nodes, H=128.
// GEMM on tensor cores via mma.sync m16n8k8 tf32, 3-term split (fp32-accurate).
// Hi/lo fragments interleaved in smem -> one LDS.128 feeds both MMAs.
// ---------------------------------------------------------------------------

#define Bg   128
#define Npg  1024
#define Hd   128
#define NN1  (Bg*Npg)        // 131072
#define NN2  (Bg*512)        // 65536
#define NN3  (Bg*256)        // 32768
#define EMAX 1048576

// ------------------------- device scratch (no allocs) ----------------------
__device__ __align__(128) float g_h [NN1*Hd];   // h = (x @ W) * dinv[row]
__device__ __align__(128) float g_cv[NN1*Hd];   // conv output (relu'd)
__device__ __align__(128) float g_xs1[NN2*Hd];
__device__ __align__(128) float g_xs2[NN3*Hd];
__device__ __align__(128) float g_xs3[(Bg*128)*Hd];
__device__ __align__(16) float g_bf[3*32768];   // W frags {hi0,hi1,lo0,lo1}
__device__ float g_dinv[NN1];
__device__ float g_sc[NN1];
__device__ int   g_newid[NN1];
__device__ int   g_cnt[NN1];
__device__ int   g_start[NN1];
__device__ int   g_cursor[NN1];
__device__ int   g_bsum[256];
__device__ int   g_src[EMAX];
__device__ int   g_r0[EMAX], g_c0[EMAX];
__device__ int   g_r1[EMAX], g_c1[EMAX];
__device__ int   g_nE[2];
__device__ float g_pinv[3];

// --------------------------- helpers ----------------------------------------
__device__ __forceinline__ float tf32r(float v) {
    float h;
    asm("cvt.rna.tf32.f32 %0, %1;" : "=f"(h) : "f"(v));
    return h;
}

__device__ __forceinline__ void mma8(float* c, const float4 a, const float2 b) {
    asm volatile(
        "mma.sync.aligned.m16n8k8.row.col.f32.tf32.tf32.f32 "
        "{%0,%1,%2,%3}, {%4,%5,%6,%7}, {%8,%9}, {%0,%1,%2,%3};"
        : "+f"(c[0]), "+f"(c[1]), "+f"(c[2]), "+f"(c[3])
        : "r"(__float_as_uint(a.x)), "r"(__float_as_uint(a.y)),
          "r"(__float_as_uint(a.z)), "r"(__float_as_uint(a.w)),
          "r"(__float_as_uint(b.x)), "r"(__float_as_uint(b.y)));
}

// -------- W -> fragment-order interleaved tf32 hi/lo (once per run) ----------
// Per layer: [kc(4)][nt(16)][ks(4)][lane(32)][4] = 32768 floats.
// slot j: 0 -> hi,k+0 ; 1 -> hi,k+4 ; 2 -> lo,k+0 ; 3 -> lo,k+4
// where k = kc*32 + ks*8 + (l&3), n = nt*8 + (l>>2).
__global__ void wsplit_k(const float* __restrict__ W1, const float* __restrict__ W2,
                         const float* __restrict__ W3, float* __restrict__ bf) {
    int layer = blockIdx.x >> 8;          // grid = 768, block = 128
    int idx = (blockIdx.x & 255) * 128 + threadIdx.x;   // 0..32767
    const float* W = (layer == 0) ? W1 : (layer == 1) ? W2 : W3;
    int j  = idx & 3;
    int l  = (idx >> 2) & 31;
    int ks = (idx >> 7) & 3;
    int nt = (idx >> 9) & 15;
    int kc = idx >> 13;
    int k = kc * 32 + ks * 8 + (l & 3) + ((j & 1) << 2);
    int n = nt * 8 + (l >> 2);
    float v = W[k * 128 + n];
    float h = tf32r(v);
    bf[layer * 32768 + idx] = (j < 2) ? h : (v - h);
}

// --------------------------- mma.sync GEMM ----------------------------------
// Out[row0+r][n] = sum_k X[r,k]*W[k,n] * rsqrt(cnt[row]+1).
// 128-row tile, 8 warps; warp w owns m-tile w (16 rows) x 128 cols.
__global__ void __launch_bounds__(256, 2)
gemm_mma(const float* __restrict__ X, const float* __restrict__ Bf,
         const int* __restrict__ cnt, float* __restrict__ Out)
{
    __shared__ float sA[8*4*32*8];   // [mt][ks][lane][8] {ah0..3, al0..3} 32KB
    __shared__ float sB[16*4*32*4];  // [nt][ks][lane][4] {bh0,bh1,bl0,bl1} 32KB
    const int tid = threadIdx.x;
    const int w = tid >> 5, l = tid & 31;
    const long row0 = (long)blockIdx.x * 128;

    float acc[16][4];
#pragma unroll
    for (int nt = 0; nt < 16; nt++)
#pragma unroll
        for (int j = 0; j < 4; j++) acc[nt][j] = 0.f;

    for (int kc = 0; kc < 4; kc++) {
        __syncthreads();               // previous chunk's compute done
        // stage A fragments (hi/lo split, interleaved): 4 frags per thread
#pragma unroll
        for (int i = 0; i < 4; i++) {
            int f = tid + i * 256;                 // 0..1023
            int fl = f & 31, ks = (f >> 5) & 3, mt = f >> 7;
            long row = row0 + mt * 16 + (fl >> 2);
            int k = kc * 32 + ks * 8 + (fl & 3);
            float v0 = X[row * 128 + k];
            float v1 = X[(row + 8) * 128 + k];
            float v2 = X[row * 128 + k + 4];
            float v3 = X[(row + 8) * 128 + k + 4];
            float h0 = tf32r(v0), h1 = tf32r(v1), h2 = tf32r(v2), h3 = tf32r(v3);
            int o = f * 8;
            *(float4*)&sA[o]     = make_float4(h0, h1, h2, h3);
            *(float4*)&sA[o + 4] = make_float4(v0 - h0, v1 - h1, v2 - h2, v3 - h3);
        }
        // stage B fragments: straight float4 copies (pre-fragmented in global).
        // sB holds 8192 floats = 2048 float4s -> 8 iterations of 256 threads.
        const float4* sbf = (const float4*)(Bf + kc * 8192);
#pragma unroll
        for (int i = 0; i < 8; i++) {
            int f = tid + i * 256;                 // 0..2047 float4s
            ((float4*)sB)[f] = sbf[f];
        }
        __syncthreads();

#pragma unroll
        for (int ks = 0; ks < 4; ks++) {
            const float4* ap = (const float4*)&sA[((w * 4 + ks) * 32 + l) * 8];
            float4 ah = ap[0];
            float4 al = ap[1];
#pragma unroll
            for (int nt = 0; nt < 16; nt++) {
                float4 bq = *(const float4*)&sB[((nt * 4 + ks) * 32 + l) * 4];
                float2 bh = make_float2(bq.x, bq.y);
                float2 bl = make_float2(bq.z, bq.w);
                mma8(acc[nt], ah, bh);
                mma8(acc[nt], ah, bl);
                mma8(acc[nt], al, bh);
            }
        }
    }

    // epilogue: c0 at (row=l>>2, col=nt*8+(l&3)*2), c1 col+1, c2/c3 row+8
    int r0 = (int)row0 + w * 16 + (l >> 2);
    float dv0 = rsqrtf((float)__ldg(&cnt[r0]) + 1.0f);
    float dv1 = rsqrtf((float)__ldg(&cnt[r0 + 8]) + 1.0f);
#pragma unroll
    for (int nt = 0; nt < 16; nt++) {
        int col = nt * 8 + (l & 3) * 2;
        *(float2*)&Out[(long)r0 * 128 + col] =
            make_float2(acc[nt][0] * dv0, acc[nt][1] * dv0);
        *(float2*)&Out[(long)(r0 + 8) * 128 + col] =
            make_float2(acc[nt][2] * dv1, acc[nt][3] * dv1);
    }
}

// ------------------------- CSR build: hist / scan ---------------------------
__global__ void hist_k(const int* __restrict__ col, int* __restrict__ cnt, int nE) {
    int i = blockIdx.x * blockDim.x + threadIdx.x;
    if (i < nE) atomicAdd(&cnt[col[i]], 1);
}

__global__ void scanA_k(const int* __restrict__ cnt, int* __restrict__ start,
                        int* __restrict__ bsum) {
    __shared__ int s[1024];
    int t = threadIdx.x;
    int i = blockIdx.x * 1024 + t;
    int v = cnt[i];
    s[t] = v;
    __syncthreads();
    for (int o = 1; o < 1024; o <<= 1) {
        int add = (t >= o) ? s[t - o] : 0;
        __syncthreads();
        s[t] += add;
        __syncthreads();
    }
    start[i] = s[t] - v;
    if (t == 1023) bsum[blockIdx.x] = s[t];
}

__global__ void scanB_k(int* bsum, int nb) {   // <<<1,128>>>, nb <= 128
    __shared__ int s[128];
    int t = threadIdx.x;
    int v = (t < nb) ? bsum[t] : 0;
    s[t] = v;
    __syncthreads();
    for (int o = 1; o < 128; o <<= 1) {
        int add = (t >= o) ? s[t - o] : 0;
        __syncthreads();
        s[t] += add;
        __syncthreads();
    }
    if (t < nb) bsum[t] = s[t] - v;
}

__global__ void scanC_k(int* __restrict__ start, const int* __restrict__ bsum,
                        const int* __restrict__ cnt, float* __restrict__ dinv, int n) {
    int i = blockIdx.x * blockDim.x + threadIdx.x;
    if (i >= n) return;
    start[i] += bsum[i >> 10];
    dinv[i] = rsqrtf((float)cnt[i] + 1.0f);
}

__global__ void fill_k(const int* __restrict__ row, const int* __restrict__ col,
                       const int* __restrict__ start, int* __restrict__ cursor,
                       int* __restrict__ src, const int* __restrict__ boundPtr,
                       int maxE) {
    int i = blockIdx.x * blockDim.x + threadIdx.x;
    int bound = boundPtr ? __ldg(boundPtr) : maxE;
    if (i >= bound) return;
    int c = col[i];
    int p = atomicAdd(&cursor[c], 1);
    src[start[c] + p] = row[i];
}

// ---- gather (h is dinv-prescaled) + self + bias + relu + score, fused ------
__global__ void gather_k(const float* __restrict__ h, const int* __restrict__ start,
                         const int* __restrict__ cnt, const int* __restrict__ src,
                         const float* __restrict__ dinv, const float* __restrict__ b,
                         const float* __restrict__ p, const float* __restrict__ pinv,
                         float* __restrict__ out, float* __restrict__ score, int n) {
    int w = (blockIdx.x * blockDim.x + threadIdx.x) >> 5;
    if (w >= n) return;
    int lane = threadIdx.x & 31;
    float dc = dinv[w];
    int s0 = start[w], d = cnt[w];
    float4 acc = ((const float4*)(h + (long)w * Hd))[lane];  // self (prescaled)

    int e = 0;
    for (; e + 4 <= d; e += 4) {
        int r0 = __ldg(&src[s0 + e]);
        int r1 = __ldg(&src[s0 + e + 1]);
        int r2 = __ldg(&src[s0 + e + 2]);
        int r3 = __ldg(&src[s0 + e + 3]);
        float4 v0 = ((const float4*)(h + (long)r0 * Hd))[lane];
        float4 v1 = ((const float4*)(h + (long)r1 * Hd))[lane];
        float4 v2 = ((const float4*)(h + (long)r2 * Hd))[lane];
        float4 v3 = ((const float4*)(h + (long)r3 * Hd))[lane];
        acc.x += v0.x + v1.x + v2.x + v3.x;
        acc.y += v0.y + v1.y + v2.y + v3.y;
        acc.z += v0.z + v1.z + v2.z + v3.z;
        acc.w += v0.w + v1.w + v2.w + v3.w;
    }
    for (; e < d; e++) {
        int r = __ldg(&src[s0 + e]);
        float4 v = ((const float4*)(h + (long)r * Hd))[lane];
        acc.x += v.x; acc.y += v.y; acc.z += v.z; acc.w += v.w;
    }

    float4 bv = ((const float4*)b)[lane];
    acc.x = fmaxf(fmaf(acc.x, dc, bv.x), 0.f);
    acc.y = fmaxf(fmaf(acc.y, dc, bv.y), 0.f);
    acc.z = fmaxf(fmaf(acc.z, dc, bv.z), 0.f);
    acc.w = fmaxf(fmaf(acc.w, dc, bv.w), 0.f);
    ((float4*)(out + (long)w * Hd))[lane] = acc;

    float4 pv = ((const float4*)p)[lane];
    float s = acc.x*pv.x + acc.y*pv.y + acc.z*pv.z + acc.w*pv.w;
#pragma unroll
    for (int o = 16; o; o >>= 1) s += __shfl_xor_sync(0xffffffffu, s, o);
    if (lane == 0) score[w] = s * __ldg(pinv);
}

// ------------------------------ p norms (all 3) -----------------------------
__global__ void pnorm3_k(const float* __restrict__ p1, const float* __restrict__ p2,
                         const float* __restrict__ p3) {   // <<<3,128>>>
    __shared__ float s[128];
    const float* p = (blockIdx.x == 0) ? p1 : (blockIdx.x == 1) ? p2 : p3;
    float v = p[threadIdx.x];
    s[threadIdx.x] = v * v;
    __syncthreads();
    for (int o = 64; o > 0; o >>= 1) {
        if (threadIdx.x < o) s[threadIdx.x] += s[threadIdx.x + o];
        __syncthreads();
    }
    if (threadIdx.x == 0) g_pinv[blockIdx.x] = rsqrtf(s[0]);
}

// ------- top-k (matches jax.lax.top_k) + readout + next-layer zeroing -------
__global__ void topk_k(const float* __restrict__ x, const float* __restrict__ score,
                       float* __restrict__ xs, int* __restrict__ newid,
                       int n_per, int k,
                       float* __restrict__ out, int addFlag,
                       int* __restrict__ cnt_next, int* __restrict__ cursor_next,
                       int* __restrict__ counter_next, int n_next) {
    __shared__ unsigned long long keys[1024];
    int g = blockIdx.x, t = threadIdx.x;
    int base = g * n_per;
    int gid = base + t;

    if (n_next > 0) {
        if (gid < n_next) { cnt_next[gid] = 0; cursor_next[gid] = 0; }
        if (gid == 0) *counter_next = 0;
    }

    newid[gid] = -1;
    float s = score[gid];
    unsigned int fb = __float_as_uint(s);
    unsigned int mp = (fb & 0x80000000u) ? ~fb : (fb | 0x80000000u);
    keys[t] = ((unsigned long long)(~mp) << 32) | (unsigned int)t;
    __syncthreads();

    for (int kk = 2; kk <= n_per; kk <<= 1) {
        for (int j = kk >> 1; j > 0; j >>= 1) {
            int ixj = t ^ j;
            if (ixj > t) {
                bool up = ((t & kk) == 0);
                unsigned long long a = keys[t], bq = keys[ixj];
                if ((a > bq) == up) { keys[t] = bq; keys[ixj] = a; }
            }
            __syncthreads();
        }
    }

    if (t < k) {
        int sel = (int)(keys[t] & 0xffffffffu);
        newid[base + sel] = g * k + t;
    }
    __syncthreads();

    int total = k * Hd;
    for (int idx = t; idx < total; idx += n_per) {
        int rank = idx >> 7, f = idx & 127;
        int sel = (int)(keys[rank] & 0xffffffffu);
        float tv = tanhf(score[base + sel]);
        xs[((long)(g * k + rank)) * Hd + f] = x[((long)(base + sel)) * Hd + f] * tv;
    }
    __syncthreads();

    if (t < 128) {
        const float* pr = xs + (long)g * k * Hd + t;
        float mx = -3.402823466e+38f, sm = 0.f;
        for (int r = 0; r < k; r++) {
            float v = pr[(long)r * Hd];
            mx = fmaxf(mx, v);
            sm += v;
        }
        float mean = sm / (float)k;
        if (addFlag) { out[g*256 + t] += mx; out[g*256 + 128 + t] += mean; }
        else         { out[g*256 + t]  = mx; out[g*256 + 128 + t]  = mean; }
    }
}

// ---- edge compaction (relabel + filter) + histogram of next layer ----------
__global__ void compact_k(const int* __restrict__ row, const int* __restrict__ col,
                          const int* __restrict__ newid,
                          int* __restrict__ orow, int* __restrict__ ocol,
                          int* __restrict__ cnt_next, int* __restrict__ counter,
                          const int* __restrict__ boundPtr, int maxE) {
    int e = blockIdx.x * blockDim.x + threadIdx.x;
    int bound = boundPtr ? __ldg(boundPtr) : maxE;
    bool valid = (e < bound);
    int nr = -1, nc = -1;
    if (valid) {
        nr = newid[row[e]];
        nc = newid[col[e]];
        valid = (nr >= 0) && (nc >= 0);
    }
    unsigned m = __ballot_sync(0xffffffffu, valid);
    if (valid) {
        int lane = threadIdx.x & 31;
        int leader = __ffs(m) - 1;
        int prefix = __popc(m & ((1u << lane) - 1u));
        int basep = 0;
        if (lane == leader) basep = atomicAdd(counter, __popc(m));
        basep = __shfl_sync(m, basep, leader);
        int pos = basep + prefix;
        orow[pos] = nr;
        ocol[pos] = nc;
        atomicAdd(&cnt_next[nc], 1);
    }
}

// ------------------------------- driver ------------------------------------
static inline int ceil_div(int a, int b) { return (a + b - 1) / b; }

struct Scratch {
    float *h, *cv, *xs1, *xs2, *xs3, *dinv, *sc, *pinv, *bf;
    int *nid, *cnt, *start, *cursor, *bsum, *src, *r0, *c0, *r1, *c1, *nE;
};

static void csr_and_conv(const Scratch& S, const float* xin, int n,
                         const int* erow, const int* ecol,
                         const int* boundPtr, int maxE,
                         int layer, const float* b, const float* p)
{
    gemm_mma<<<n / 128, 256>>>(xin, S.bf + layer * 32768, S.cnt, S.h);
    scanA_k<<<n / 1024, 1024>>>(S.cnt, S.start, S.bsum);
    scanB_k<<<1, 128>>>(S.bsum, n / 1024);
    scanC_k<<<ceil_div(n, 256), 256>>>(S.start, S.bsum, S.cnt, S.dinv, n);
    fill_k<<<ceil_div(maxE, 256), 256>>>(erow, ecol, S.start, S.cursor, S.src,
                                         boundPtr, maxE);
    gather_k<<<ceil_div(n * 32, 256), 256>>>(S.h, S.start, S.cnt, S.src,
                                             S.dinv, b, p, S.pinv + layer,
                                             S.cv, S.sc, n);
}

extern "C" void kernel_launch(void* const* d_in, const int* in_sizes, int n_in,
                              void* d_out, int out_size)
{
    const float* x    = (const float*)d_in[0];
    const int*   erow = (const int*)  d_in[1];
    const int*   ecol = (const int*)  d_in[2];
    const float* W1 = (const float*)d_in[3],  *b1 = (const float*)d_in[4],  *p1 = (const float*)d_in[5];
    const float* W2 = (const float*)d_in[6],  *b2 = (const float*)d_in[7],  *p2 = (const float*)d_in[8];
    const float* W3 = (const float*)d_in[9],  *b3 = (const float*)d_in[10], *p3 = (const float*)d_in[11];
    float* out = (float*)d_out;
    const int E = in_sizes[1];

    Scratch S;
    cudaGetSymbolAddress((void**)&S.h,      g_h);
    cudaGetSymbolAddress((void**)&S.cv,     g_cv);
    cudaGetSymbolAddress((void**)&S.xs1,    g_xs1);
    cudaGetSymbolAddress((void**)&S.xs2,    g_xs2);
    cudaGetSymbolAddress((void**)&S.xs3,    g_xs3);
    cudaGetSymbolAddress((void**)&S.bf,     g_bf);
    cudaGetSymbolAddress((void**)&S.dinv,   g_dinv);
    cudaGetSymbolAddress((void**)&S.sc,     g_sc);
    cudaGetSymbolAddress((void**)&S.pinv,   g_pinv);
    cudaGetSymbolAddress((void**)&S.nid,    g_newid);
    cudaGetSymbolAddress((void**)&S.cnt,    g_cnt);
    cudaGetSymbolAddress((void**)&S.start,  g_start);
    cudaGetSymbolAddress((void**)&S.cursor, g_cursor);
    cudaGetSymbolAddress((void**)&S.bsum,   g_bsum);
    cudaGetSymbolAddress((void**)&S.src,    g_src);
    cudaGetSymbolAddress((void**)&S.r0,     g_r0);
    cudaGetSymbolAddress((void**)&S.c0,     g_c0);
    cudaGetSymbolAddress((void**)&S.r1,     g_r1);
    cudaGetSymbolAddress((void**)&S.c1,     g_c1);
    cudaGetSymbolAddress((void**)&S.nE,     g_nE);

    // ---------------- Layer 1: n=131072, keep 512/1024 ----------------
    // gemm_mma is the 6th graph node (ncu -s 5 -c 1 profiles it).
    wsplit_k<<<768, 128>>>(W1, W2, W3, S.bf);                    // 1
    cudaMemsetAsync(S.cnt, 0, NN1 * sizeof(int));                // 2
    cudaMemsetAsync(S.cursor, 0, NN1 * sizeof(int));             // 3
    hist_k<<<ceil_div(E, 256), 256>>>(ecol, S.cnt, E);           // 4
    scanA_k<<<NN1 / 1024, 1024>>>(S.cnt, S.start, S.bsum);       // 5
    gemm_mma<<<NN1 / 128, 256>>>(x, S.bf, S.cnt, S.h);           // 6  <- profiled
    pnorm3_k<<<3, 128>>>(p1, p2, p3);
    scanB_k<<<1, 128>>>(S.bsum, NN1 / 1024);
    scanC_k<<<ceil_div(NN1, 256), 256>>>(S.start, S.bsum, S.cnt, S.dinv, NN1);
    fill_k<<<ceil_div(E, 256), 256>>>(erow, ecol, S.start, S.cursor, S.src,
                                      nullptr, E);
    gather_k<<<ceil_div(NN1 * 32, 256), 256>>>(S.h, S.start, S.cnt, S.src,
                                               S.dinv, b1, p1, S.pinv + 0,
                                               S.cv, S.sc, NN1);
    topk_k<<<Bg, 1024>>>(S.cv, S.sc, S.xs1, S.nid, 1024, 512, out, 0,
                         S.cnt, S.cursor, S.nE + 0, NN2);
    compact_k<<<ceil_div(E, 256), 256>>>(erow, ecol, S.nid, S.r0, S.c0,
                                         S.cnt, S.nE + 0, nullptr, E);

    // ---------------- Layer 2: n=65536, keep 256/512 ----------------
    csr_and_conv(S, S.xs1, NN2, S.r0, S.c0, S.nE + 0, E, 1, b2, p2);
    topk_k<<<Bg, 512>>>(S.cv, S.sc, S.xs2, S.nid, 512, 256, out, 1,
                        S.cnt, S.cursor, S.nE + 1, NN3);
    compact_k<<<ceil_div(E, 256), 256>>>(S.r0, S.c0, S.nid, S.r1, S.c1,
                                         S.cnt, S.nE + 1, S.nE + 0, E);

    // ---------------- Layer 3: n=32768, keep 128/256 ----------------
    csr_and_conv(S, S.xs2, NN3, S.r1, S.c1, S.nE + 1, E, 2, b3, p3);
    topk_k<<<Bg, 256>>>(S.cv, S.sc, S.xs3, S.nid, 256, 128, out, 1,
                        nullptr, nullptr, nullptr, 0);
}

// round 12
// speedup vs baseline: 1.5109x; 1.1208x over previous
#include <cuda_runtime.h>
#include <cuda_bf16.h>
#include <cstdint>
#include <math.h>

// ---------------------------------------------------------------------------
// GCN + TopK pooling stack (3 layers), B=128 graphs, N=1024 nodes, H=128.
// GEMM: mma.sync m16n8k8 tf32 3-term split. Single-kernel lookback scan.
// Warp-shfl bitonic topk.
// ---------------------------------------------------------------------------

#define Bg   128
#define Npg  1024
#define Hd   128
#define NN1  (Bg*Npg)        // 131072
#define NN2  (Bg*512)        // 65536
#define NN3  (Bg*256)        // 32768
#define EMAX 1048576

// ------------------------- device scratch (no allocs) ----------------------
__device__ __align__(128) float g_h [NN1*Hd];
__device__ __align__(128) float g_cv[NN1*Hd];
__device__ __align__(128) float g_xs1[NN2*Hd];
__device__ __align__(128) float g_xs2[NN3*Hd];
__device__ __align__(128) float g_xs3[(Bg*128)*Hd];
__device__ __align__(16) float g_bf[3*32768];   // W frags {hi0,hi1,lo0,lo1}
__device__ float g_dinv[NN1];
__device__ float g_sc[NN1];
__device__ int   g_newid[NN1];
__device__ int   g_cnt[NN1];
__device__ int   g_start[NN1];
__device__ int   g_cursor[NN1];
__device__ unsigned long long g_tstate[3*128];   // lookback scan states
__device__ int   g_src[EMAX];
__device__ int   g_r0[EMAX], g_c0[EMAX];
__device__ int   g_r1[EMAX], g_c1[EMAX];
__device__ int   g_nE[2];
__device__ float g_pinv[3];

// --------------------------- helpers ----------------------------------------
__device__ __forceinline__ float tf32r(float v) {
    float h;
    asm("cvt.rna.tf32.f32 %0, %1;" : "=f"(h) : "f"(v));
    return h;
}

__device__ __forceinline__ void mma8(float* c, const float4 a, const float2 b) {
    asm volatile(
        "mma.sync.aligned.m16n8k8.row.col.f32.tf32.tf32.f32 "
        "{%0,%1,%2,%3}, {%4,%5,%6,%7}, {%8,%9}, {%0,%1,%2,%3};"
        : "+f"(c[0]), "+f"(c[1]), "+f"(c[2]), "+f"(c[3])
        : "r"(__float_as_uint(a.x)), "r"(__float_as_uint(a.y)),
          "r"(__float_as_uint(a.z)), "r"(__float_as_uint(a.w)),
          "r"(__float_as_uint(b.x)), "r"(__float_as_uint(b.y)));
}

// ---- W frag split + pnorm + replay zero-init, one kernel (grid 779) --------
// blocks 0..767: W fragments. 768..770: pnorm. 771..778: zero cnt/cursor/tstate.
__global__ void wsplit_k(const float* __restrict__ W1, const float* __restrict__ W2,
                         const float* __restrict__ W3,
                         const float* __restrict__ p1, const float* __restrict__ p2,
                         const float* __restrict__ p3,
                         float* __restrict__ bf, int* __restrict__ cnt,
                         int* __restrict__ cursor, unsigned long long* __restrict__ ts) {
    __shared__ float sp[128];
    int bid = blockIdx.x, t = threadIdx.x;
    if (bid < 768) {
        int layer = bid >> 8;
        int idx = (bid & 255) * 128 + t;          // 0..32767
        const float* W = (layer == 0) ? W1 : (layer == 1) ? W2 : W3;
        int j  = idx & 3;
        int l  = (idx >> 2) & 31;
        int ks = (idx >> 7) & 3;
        int nt = (idx >> 9) & 15;
        int kc = idx >> 13;
        int k = kc * 32 + ks * 8 + (l & 3) + ((j & 1) << 2);
        int n = nt * 8 + (l >> 2);
        float v = W[k * 128 + n];
        float h = tf32r(v);
        bf[layer * 32768 + idx] = (j < 2) ? h : (v - h);
    } else if (bid < 771) {
        const float* p = (bid == 768) ? p1 : (bid == 769) ? p2 : p3;
        float v = p[t];
        sp[t] = v * v;
        __syncthreads();
        for (int o = 64; o > 0; o >>= 1) {
            if (t < o) sp[t] += sp[t + o];
            __syncthreads();
        }
        if (t == 0) g_pinv[bid - 768] = rsqrtf(sp[0]);
    } else {
        int z = (bid - 771) * 128 + t;            // 0..1023
        int4 z4 = make_int4(0, 0, 0, 0);
        for (int q = z; q < NN1 / 4; q += 1024) {
            ((int4*)cnt)[q] = z4;
            ((int4*)cursor)[q] = z4;
        }
        if (z < 384) ts[z] = 0ull;
    }
}

// --------------------------- mma.sync GEMM ----------------------------------
__global__ void __launch_bounds__(256, 2)
gemm_mma(const float* __restrict__ X, const float* __restrict__ Bf,
         const int* __restrict__ cnt, float* __restrict__ Out)
{
    __shared__ float sA[8*4*32*8];   // [mt][ks][lane][8] {ah0..3, al0..3} 32KB
    __shared__ float sB[16*4*32*4];  // [nt][ks][lane][4] {bh0,bh1,bl0,bl1} 32KB
    const int tid = threadIdx.x;
    const int w = tid >> 5, l = tid & 31;
    const long row0 = (long)blockIdx.x * 128;

    float acc[16][4];
#pragma unroll
    for (int nt = 0; nt < 16; nt++)
#pragma unroll
        for (int j = 0; j < 4; j++) acc[nt][j] = 0.f;

    for (int kc = 0; kc < 4; kc++) {
        __syncthreads();
#pragma unroll
        for (int i = 0; i < 4; i++) {
            int f = tid + i * 256;
            int fl = f & 31, ks = (f >> 5) & 3, mt = f >> 7;
            long row = row0 + mt * 16 + (fl >> 2);
            int k = kc * 32 + ks * 8 + (fl & 3);
            float v0 = X[row * 128 + k];
            float v1 = X[(row + 8) * 128 + k];
            float v2 = X[row * 128 + k + 4];
            float v3 = X[(row + 8) * 128 + k + 4];
            float h0 = tf32r(v0), h1 = tf32r(v1), h2 = tf32r(v2), h3 = tf32r(v3);
            int o = f * 8;
            *(float4*)&sA[o]     = make_float4(h0, h1, h2, h3);
            *(float4*)&sA[o + 4] = make_float4(v0 - h0, v1 - h1, v2 - h2, v3 - h3);
        }
        const float4* sbf = (const float4*)(Bf + kc * 8192);
#pragma unroll
        for (int i = 0; i < 8; i++) {
            int f = tid + i * 256;
            ((float4*)sB)[f] = sbf[f];
        }
        __syncthreads();

#pragma unroll
        for (int ks = 0; ks < 4; ks++) {
            const float4* ap = (const float4*)&sA[((w * 4 + ks) * 32 + l) * 8];
            float4 ah = ap[0];
            float4 al = ap[1];
#pragma unroll
            for (int nt = 0; nt < 16; nt++) {
                float4 bq = *(const float4*)&sB[((nt * 4 + ks) * 32 + l) * 4];
                float2 bh = make_float2(bq.x, bq.y);
                float2 bl = make_float2(bq.z, bq.w);
                mma8(acc[nt], ah, bh);
                mma8(acc[nt], ah, bl);
                mma8(acc[nt], al, bh);
            }
        }
    }

    int r0 = (int)row0 + w * 16 + (l >> 2);
    float dv0 = rsqrtf((float)__ldg(&cnt[r0]) + 1.0f);
    float dv1 = rsqrtf((float)__ldg(&cnt[r0 + 8]) + 1.0f);
#pragma unroll
    for (int nt = 0; nt < 16; nt++) {
        int col = nt * 8 + (l & 3) * 2;
        *(float2*)&Out[(long)r0 * 128 + col] =
            make_float2(acc[nt][0] * dv0, acc[nt][1] * dv0);
        *(float2*)&Out[(long)(r0 + 8) * 128 + col] =
            make_float2(acc[nt][2] * dv1, acc[nt][3] * dv1);
    }
}

// --------------------------- hist -------------------------------------------
__global__ void hist_k(const int* __restrict__ col, int* __restrict__ cnt, int nE) {
    int i = blockIdx.x * blockDim.x + threadIdx.x;
    if (i < nE) atomicAdd(&cnt[col[i]], 1);
}

// ---- single-kernel exclusive scan (decoupled lookback; grid <= 128) --------
__global__ void scan_k(const int* __restrict__ cnt, int* __restrict__ start,
                       float* __restrict__ dinv, unsigned long long* __restrict__ st)
{
    __shared__ int s[1024];
    __shared__ int s_prefix;
    int t = threadIdx.x, b = blockIdx.x;
    int i = b * 1024 + t;
    int v = cnt[i];
    s[t] = v;
    __syncthreads();
    for (int o = 1; o < 1024; o <<= 1) {
        int add = (t >= o) ? s[t - o] : 0;
        __syncthreads();
        s[t] += add;
        __syncthreads();
    }
    if (t == 0) {
        int total = s[1023];
        atomicExch(&st[b], (((unsigned long long)total) << 2) | 1ull);  // PARTIAL
        int ex = 0;
        for (int j = b - 1; j >= 0; j--) {
            unsigned long long f;
            do { f = atomicAdd(&st[j], 0ull); } while ((f & 3ull) == 0ull);
            ex += (int)(f >> 2);
            if ((f & 3ull) == 2ull) break;       // PREFIX: inclusive, stop
        }
        atomicExch(&st[b], (((unsigned long long)(ex + total)) << 2) | 2ull);
        s_prefix = ex;
    }
    __syncthreads();
    start[i] = s[t] - v + s_prefix;
    dinv[i] = rsqrtf((float)v + 1.0f);
}

__global__ void fill_k(const int* __restrict__ row, const int* __restrict__ col,
                       const int* __restrict__ start, int* __restrict__ cursor,
                       int* __restrict__ src, const int* __restrict__ boundPtr,
                       int maxE) {
    int i = blockIdx.x * blockDim.x + threadIdx.x;
    int bound = boundPtr ? __ldg(boundPtr) : maxE;
    if (i >= bound) return;
    int c = col[i];
    int p = atomicAdd(&cursor[c], 1);
    src[start[c] + p] = row[i];
}

// ---- gather (h is dinv-prescaled) + self + bias + relu + score, fused ------
__global__ void gather_k(const float* __restrict__ h, const int* __restrict__ start,
                         const int* __restrict__ cnt, const int* __restrict__ src,
                         const float* __restrict__ dinv, const float* __restrict__ b,
                         const float* __restrict__ p, const float* __restrict__ pinv,
                         float* __restrict__ out, float* __restrict__ score, int n) {
    int w = (blockIdx.x * blockDim.x + threadIdx.x) >> 5;
    if (w >= n) return;
    int lane = threadIdx.x & 31;
    float dc = dinv[w];
    int s0 = start[w], d = cnt[w];
    float4 acc = ((const float4*)(h + (long)w * Hd))[lane];

    int e = 0;
    for (; e + 4 <= d; e += 4) {
        int r0 = __ldg(&src[s0 + e]);
        int r1 = __ldg(&src[s0 + e + 1]);
        int r2 = __ldg(&src[s0 + e + 2]);
        int r3 = __ldg(&src[s0 + e + 3]);
        float4 v0 = ((const float4*)(h + (long)r0 * Hd))[lane];
        float4 v1 = ((const float4*)(h + (long)r1 * Hd))[lane];
        float4 v2 = ((const float4*)(h + (long)r2 * Hd))[lane];
        float4 v3 = ((const float4*)(h + (long)r3 * Hd))[lane];
        acc.x += v0.x + v1.x + v2.x + v3.x;
        acc.y += v0.y + v1.y + v2.y + v3.y;
        acc.z += v0.z + v1.z + v2.z + v3.z;
        acc.w += v0.w + v1.w + v2.w + v3.w;
    }
    for (; e < d; e++) {
        int r = __ldg(&src[s0 + e]);
        float4 v = ((const float4*)(h + (long)r * Hd))[lane];
        acc.x += v.x; acc.y += v.y; acc.z += v.z; acc.w += v.w;
    }

    float4 bv = ((const float4*)b)[lane];
    acc.x = fmaxf(fmaf(acc.x, dc, bv.x), 0.f);
    acc.y = fmaxf(fmaf(acc.y, dc, bv.y), 0.f);
    acc.z = fmaxf(fmaf(acc.z, dc, bv.z), 0.f);
    acc.w = fmaxf(fmaf(acc.w, dc, bv.w), 0.f);
    ((float4*)(out + (long)w * Hd))[lane] = acc;

    float4 pv = ((const float4*)p)[lane];
    float s = acc.x*pv.x + acc.y*pv.y + acc.z*pv.z + acc.w*pv.w;
#pragma unroll
    for (int o = 16; o; o >>= 1) s += __shfl_xor_sync(0xffffffffu, s, o);
    if (lane == 0) score[w] = s * __ldg(pinv);
}

// ------- top-k (matches jax.lax.top_k) + readout + next-layer zeroing -------
// Bitonic sort: stages with j<=16 run in registers via shfl.bfly.
__global__ void topk_k(const float* __restrict__ x, const float* __restrict__ score,
                       float* __restrict__ xs, int* __restrict__ newid,
                       int n_per, int k,
                       float* __restrict__ out, int addFlag,
                       int* __restrict__ cnt_next, int* __restrict__ cursor_next,
                       int* __restrict__ counter_next, int n_next) {
    __shared__ unsigned long long keys[1024];
    __shared__ float tv_s[512];
    __shared__ int   sel_s[512];
    int g = blockIdx.x, t = threadIdx.x;
    int base = g * n_per;
    int gid = base + t;

    if (n_next > 0) {
        if (gid < n_next) { cnt_next[gid] = 0; cursor_next[gid] = 0; }
        if (gid == 0) *counter_next = 0;
    }

    newid[gid] = -1;
    float s = score[gid];
    unsigned int fb = __float_as_uint(s);
    unsigned int mp = (fb & 0x80000000u) ? ~fb : (fb | 0x80000000u);
    unsigned long long key = ((unsigned long long)(~mp) << 32) | (unsigned int)t;

    // in-warp bitonic up to kk=32 (pairs stay within warp for j<=16)
#pragma unroll
    for (int kk = 2; kk <= 32; kk <<= 1) {
#pragma unroll
        for (int j = kk >> 1; j >= 1; j >>= 1) {
            unsigned long long part = __shfl_xor_sync(0xffffffffu, key, j);
            bool takeMin = (((t & j) == 0) == ((t & kk) == 0));
            key = takeMin ? (key < part ? key : part) : (key > part ? key : part);
        }
    }
    keys[t] = key;
    __syncthreads();

    for (int kk = 64; kk <= n_per; kk <<= 1) {
        for (int j = kk >> 1; j >= 32; j >>= 1) {
            int ixj = t ^ j;
            if (ixj > t) {
                bool up = ((t & kk) == 0);
                unsigned long long a = keys[t], bq = keys[ixj];
                if ((a > bq) == up) { keys[t] = bq; keys[ixj] = a; }
            }
            __syncthreads();
        }
        key = keys[t];
#pragma unroll
        for (int j = 16; j >= 1; j >>= 1) {
            unsigned long long part = __shfl_xor_sync(0xffffffffu, key, j);
            bool takeMin = (((t & j) == 0) == ((t & kk) == 0));
            key = takeMin ? (key < part ? key : part) : (key > part ? key : part);
        }
        keys[t] = key;
        __syncthreads();
    }

    if (t < k) {
        int sel = (int)(keys[t] & 0xffffffffu);
        newid[base + sel] = g * k + t;
        sel_s[t] = sel;
        tv_s[t] = tanhf(score[base + sel]);
    }
    __syncthreads();

    int total = k * Hd;
    for (int idx = t; idx < total; idx += n_per) {
        int rank = idx >> 7, f = idx & 127;
        xs[((long)(g * k + rank)) * Hd + f] =
            x[((long)(base + sel_s[rank])) * Hd + f] * tv_s[rank];
    }
    __syncthreads();

    if (t < 128) {
        const float* pr = xs + (long)g * k * Hd + t;
        float mx = -3.402823466e+38f, sm = 0.f;
        for (int r = 0; r < k; r++) {
            float v = pr[(long)r * Hd];
            mx = fmaxf(mx, v);
            sm += v;
        }
        float mean = sm / (float)k;
        if (addFlag) { out[g*256 + t] += mx; out[g*256 + 128 + t] += mean; }
        else         { out[g*256 + t]  = mx; out[g*256 + 128 + t]  = mean; }
    }
}

// ---- edge compaction (relabel + filter) + histogram of next layer ----------
__global__ void compact_k(const int* __restrict__ row, const int* __restrict__ col,
                          const int* __restrict__ newid,
                          int* __restrict__ orow, int* __restrict__ ocol,
                          int* __restrict__ cnt_next, int* __restrict__ counter,
                          const int* __restrict__ boundPtr, int maxE) {
    int e = blockIdx.x * blockDim.x + threadIdx.x;
    int bound = boundPtr ? __ldg(boundPtr) : maxE;
    bool valid = (e < bound);
    int nr = -1, nc = -1;
    if (valid) {
        nr = newid[row[e]];
        nc = newid[col[e]];
        valid = (nr >= 0) && (nc >= 0);
    }
    unsigned m = __ballot_sync(0xffffffffu, valid);
    if (valid) {
        int lane = threadIdx.x & 31;
        int leader = __ffs(m) - 1;
        int prefix = __popc(m & ((1u << lane) - 1u));
        int basep = 0;
        if (lane == leader) basep = atomicAdd(counter, __popc(m));
        basep = __shfl_sync(m, basep, leader);
        int pos = basep + prefix;
        orow[pos] = nr;
        ocol[pos] = nc;
        atomicAdd(&cnt_next[nc], 1);
    }
}

// ------------------------------- driver ------------------------------------
static inline int ceil_div(int a, int b) { return (a + b - 1) / b; }

struct Scratch {
    float *h, *cv, *xs1, *xs2, *xs3, *dinv, *sc, *pinv, *bf;
    int *nid, *cnt, *start, *cursor, *src, *r0, *c0, *r1, *c1, *nE;
    unsigned long long *ts;
};

extern "C" void kernel_launch(void* const* d_in, const int* in_sizes, int n_in,
                              void* d_out, int out_size)
{
    const float* x    = (const float*)d_in[0];
    const int*   erow = (const int*)  d_in[1];
    const int*   ecol = (const int*)  d_in[2];
    const float* W1 = (const float*)d_in[3],  *b1 = (const float*)d_in[4],  *p1 = (const float*)d_in[5];
    const float* W2 = (const float*)d_in[6],  *b2 = (const float*)d_in[7],  *p2 = (const float*)d_in[8];
    const float* W3 = (const float*)d_in[9],  *b3 = (const float*)d_in[10], *p3 = (const float*)d_in[11];
    float* out = (float*)d_out;
    const int E = in_sizes[1];

    Scratch S;
    cudaGetSymbolAddress((void**)&S.h,      g_h);
    cudaGetSymbolAddress((void**)&S.cv,     g_cv);
    cudaGetSymbolAddress((void**)&S.xs1,    g_xs1);
    cudaGetSymbolAddress((void**)&S.xs2,    g_xs2);
    cudaGetSymbolAddress((void**)&S.xs3,    g_xs3);
    cudaGetSymbolAddress((void**)&S.bf,     g_bf);
    cudaGetSymbolAddress((void**)&S.dinv,   g_dinv);
    cudaGetSymbolAddress((void**)&S.sc,     g_sc);
    cudaGetSymbolAddress((void**)&S.pinv,   g_pinv);
    cudaGetSymbolAddress((void**)&S.nid,    g_newid);
    cudaGetSymbolAddress((void**)&S.cnt,    g_cnt);
    cudaGetSymbolAddress((void**)&S.start,  g_start);
    cudaGetSymbolAddress((void**)&S.cursor, g_cursor);
    cudaGetSymbolAddress((void**)&S.ts,     g_tstate);
    cudaGetSymbolAddress((void**)&S.src,    g_src);
    cudaGetSymbolAddress((void**)&S.r0,     g_r0);
    cudaGetSymbolAddress((void**)&S.c0,     g_c0);
    cudaGetSymbolAddress((void**)&S.r1,     g_r1);
    cudaGetSymbolAddress((void**)&S.c1,     g_c1);
    cudaGetSymbolAddress((void**)&S.nE,     g_nE);

    // ---------------- Layer 1: n=131072, keep 512/1024 ----------------
    // gather_k is the 6th launch (ncu -s 5 -c 1 profiles it).
    wsplit_k<<<779, 128>>>(W1, W2, W3, p1, p2, p3, S.bf, S.cnt, S.cursor, S.ts); // 1
    hist_k<<<ceil_div(E, 256), 256>>>(ecol, S.cnt, E);                           // 2
    scan_k<<<NN1 / 1024, 1024>>>(S.cnt, S.start, S.dinv, S.ts);                  // 3
    fill_k<<<ceil_div(E, 256), 256>>>(erow, ecol, S.start, S.cursor, S.src,
                                      nullptr, E);                               // 4
    gemm_mma<<<NN1 / 128, 256>>>(x, S.bf, S.cnt, S.h);                           // 5
    gather_k<<<ceil_div(NN1 * 32, 256), 256>>>(S.h, S.start, S.cnt, S.src,
                                               S.dinv, b1, p1, S.pinv + 0,
                                               S.cv, S.sc, NN1);                 // 6 <- profiled
    topk_k<<<Bg, 1024>>>(S.cv, S.sc, S.xs1, S.nid, 1024, 512, out, 0,
                         S.cnt, S.cursor, S.nE + 0, NN2);
    compact_k<<<ceil_div(E, 256), 256>>>(erow, ecol, S.nid, S.r0, S.c0,
                                         S.cnt, S.nE + 0, nullptr, E);

    // ---------------- Layer 2: n=65536, keep 256/512 ----------------
    gemm_mma<<<NN2 / 128, 256>>>(S.xs1, S.bf + 32768, S.cnt, S.h);
    scan_k<<<NN2 / 1024, 1024>>>(S.cnt, S.start, S.dinv, S.ts + 128);
    fill_k<<<ceil_div(E, 256), 256>>>(S.r0, S.c0, S.start, S.cursor, S.src,
                                      S.nE + 0, E);
    gather_k<<<ceil_div(NN2 * 32, 256), 256>>>(S.h, S.start, S.cnt, S.src,
                                               S.dinv, b2, p2, S.pinv + 1,
                                               S.cv, S.sc, NN2);
    topk_k<<<Bg, 512>>>(S.cv, S.sc, S.xs2, S.nid, 512, 256, out, 1,
                        S.cnt, S.cursor, S.nE + 1, NN3);
    compact_k<<<ceil_div(E, 256), 256>>>(S.r0, S.c0, S.nid, S.r1, S.c1,
                                         S.cnt, S.nE + 1, S.nE + 0, E);

    // ---------------- Layer 3: n=32768, keep 128/256 ----------------
    gemm_mma<<<NN3 / 128, 256>>>(S.xs2, S.bf + 65536, S.cnt, S.h);
    scan_k<<<NN3 / 1024, 1024>>>(S.cnt, S.start, S.dinv, S.ts + 256);
    fill_k<<<ceil_div(E, 256), 256>>>(S.r1, S.c1, S.start, S.cursor, S.src,
                                      S.nE + 1, E);
    gather_k<<<ceil_div(NN3 * 32, 256), 256>>>(S.h, S.start, S.cnt, S.src,
                                               S.dinv, b3, p3, S.pinv + 2,
                                               S.cv, S.sc, NN3);
    topk_k<<<Bg, 256>>>(S.cv, S.sc, S.xs3, S.nid, 256, 128, out, 1,
                        nullptr, nullptr, nullptr, 0);
}